// round 3
// baseline (speedup 1.0000x reference)
#include <cuda_runtime.h>
#include <cuda_bf16.h>
#include <cstddef>

// ---------------------------------------------------------------------------
// GridGNNLayer: N=256 nodes, C=32, H=W=64, E=4096 edges, edge_emb=4,
// hidden=64, emb_dim=32, F=2.
//   1) k_down  : x -> xd[256,4,32,32] (2x2 s2 conv), zeroes g_agg
//   2) k_edge  : fused gather->conv3x3(8->4)+ReLU->conv3x3(4->4)+ReLU->scatter
//   3) k_up    : g_agg -> g_up[256,4,64,64] (2x2 s2 transposed conv)
//   4) k_conv3x3<36,64,...>  : concat(x,up) -> g_hidden   (FFMA2 path)
//   5) k_conv3x3<64,32,...>  : g_hidden -> out            (FFMA2 path)
// ---------------------------------------------------------------------------

#define NNODE 256
#define NEDGE 4096

typedef unsigned long long ull;

__device__ float g_xd    [NNODE * 4 * 32 * 32];                 //   4 MB
__device__ float g_agg   [NNODE * 4 * 32 * 32];                 //   4 MB
__device__ float g_up    [NNODE * 4 * 64 * 64];                 //  16 MB
__device__ float g_hidden[(size_t)NNODE * 64 * 64 * 64];        // 268 MB

// ---- packed fp32x2 helpers (sm_100+) --------------------------------------
__device__ __forceinline__ ull pk2(float a, float b) {
    ull r; asm("mov.b64 %0, {%1, %2};" : "=l"(r) : "f"(a), "f"(b)); return r;
}
__device__ __forceinline__ void fma2(ull& d, ull a, ull b) {
    asm("fma.rn.f32x2 %0, %1, %2, %0;" : "+l"(d) : "l"(a), "l"(b));
}
__device__ __forceinline__ void upk2(ull v, float& a, float& b) {
    asm("mov.b64 {%0, %1}, %2;" : "=f"(a), "=f"(b) : "l"(v));
}

// ---------------------------------------------------------------------------
// 1) downsample + zero g_agg
// ---------------------------------------------------------------------------
__global__ __launch_bounds__(256) void k_down(const float* __restrict__ x,
                                              const float* __restrict__ w,
                                              const float* __restrict__ b) {
    int idx = blockIdx.x * 256 + threadIdx.x;          // over N*32*32
    int n = idx >> 10;
    int p = (idx >> 5) & 31;
    int q = idx & 31;

    float acc0 = __ldg(b + 0), acc1 = __ldg(b + 1);
    float acc2 = __ldg(b + 2), acc3 = __ldg(b + 3);

    const float* xp = x + (size_t)n * 32 * 4096 + (2 * p) * 64 + 2 * q;
    #pragma unroll 4
    for (int c = 0; c < 32; ++c) {
        const float* r0 = xp + c * 4096;
        float v00 = r0[0], v01 = r0[1], v10 = r0[64], v11 = r0[65];
        const float* wp = w + (c << 2);
        acc0 += v00 * __ldg(wp +   0) + v01 * __ldg(wp +   1) + v10 * __ldg(wp +   2) + v11 * __ldg(wp +   3);
        acc1 += v00 * __ldg(wp + 128) + v01 * __ldg(wp + 129) + v10 * __ldg(wp + 130) + v11 * __ldg(wp + 131);
        acc2 += v00 * __ldg(wp + 256) + v01 * __ldg(wp + 257) + v10 * __ldg(wp + 258) + v11 * __ldg(wp + 259);
        acc3 += v00 * __ldg(wp + 384) + v01 * __ldg(wp + 385) + v10 * __ldg(wp + 386) + v11 * __ldg(wp + 387);
    }
    float* op = g_xd + n * 4096 + p * 32 + q;
    op[0]    = acc0; op[1024] = acc1; op[2048] = acc2; op[3072] = acc3;
    float* ap = g_agg + n * 4096 + p * 32 + q;
    ap[0] = 0.f; ap[1024] = 0.f; ap[2048] = 0.f; ap[3072] = 0.f;
}

// ---------------------------------------------------------------------------
// 2) fused edge network + scatter (unchanged from R1)
// ---------------------------------------------------------------------------
__global__ __launch_bounds__(256, 1) void k_edge(const int* __restrict__ eidx,
                                                 const float* __restrict__ we1,
                                                 const float* __restrict__ be1,
                                                 const float* __restrict__ we2,
                                                 const float* __restrict__ be2) {
    __shared__ float sIn[8][34][34];
    const int e   = blockIdx.x;
    const int row = eidx[e];
    const int col = eidx[NEDGE + e];
    const int tid = threadIdx.x;

    float* sflat = &sIn[0][0][0];
    for (int i = tid; i < 8 * 34 * 34; i += 256) sflat[i] = 0.f;
    __syncthreads();
    for (int i = tid; i < 8192; i += 256) {
        int ch = i >> 10;
        int p  = i & 1023;
        int node = (ch < 4) ? row : col;
        sIn[ch][(p >> 5) + 1][(p & 31) + 1] = g_xd[node * 4096 + (ch & 3) * 1024 + p];
    }
    __syncthreads();

    const int o    = tid >> 6;
    const int lane = tid & 63;
    const int ry   = lane >> 1;
    const int cx0  = (lane & 1) << 4;

    float w1[72];
    #pragma unroll
    for (int i = 0; i < 72; ++i) w1[i] = __ldg(we1 + o * 72 + i);
    float acc1[16];
    {
        float bv = __ldg(be1 + o);
        #pragma unroll
        for (int j = 0; j < 16; ++j) acc1[j] = bv;
    }
    #pragma unroll
    for (int ci = 0; ci < 8; ++ci) {
        float a0 = sIn[ci][ry][cx0],     aa1 = sIn[ci][ry + 1][cx0],     a2 = sIn[ci][ry + 2][cx0];
        float c0 = sIn[ci][ry][cx0 + 1], c1  = sIn[ci][ry + 1][cx0 + 1], c2 = sIn[ci][ry + 2][cx0 + 1];
        const float* wc = w1 + ci * 9;
        #pragma unroll
        for (int j = 0; j < 16; ++j) {
            float d0 = sIn[ci][ry][cx0 + 2 + j];
            float d1 = sIn[ci][ry + 1][cx0 + 2 + j];
            float d2 = sIn[ci][ry + 2][cx0 + 2 + j];
            acc1[j] += a0 * wc[0] + c0 * wc[1] + d0 * wc[2]
                     + aa1 * wc[3] + c1 * wc[4] + d1 * wc[5]
                     + a2 * wc[6] + c2 * wc[7] + d2 * wc[8];
            a0 = c0; aa1 = c1; a2 = c2;
            c0 = d0; c1 = d1; c2 = d2;
        }
    }
    __syncthreads();
    #pragma unroll
    for (int j = 0; j < 16; ++j)
        sIn[o][ry + 1][cx0 + 1 + j] = fmaxf(acc1[j], 0.f);
    __syncthreads();

    float w2[36];
    #pragma unroll
    for (int i = 0; i < 36; ++i) w2[i] = __ldg(we2 + o * 36 + i);
    float acc2[16];
    {
        float bv = __ldg(be2 + o);
        #pragma unroll
        for (int j = 0; j < 16; ++j) acc2[j] = bv;
    }
    #pragma unroll
    for (int ci = 0; ci < 4; ++ci) {
        float a0 = sIn[ci][ry][cx0],     aa1 = sIn[ci][ry + 1][cx0],     a2 = sIn[ci][ry + 2][cx0];
        float c0 = sIn[ci][ry][cx0 + 1], c1  = sIn[ci][ry + 1][cx0 + 1], c2 = sIn[ci][ry + 2][cx0 + 1];
        const float* wc = w2 + ci * 9;
        #pragma unroll
        for (int j = 0; j < 16; ++j) {
            float d0 = sIn[ci][ry][cx0 + 2 + j];
            float d1 = sIn[ci][ry + 1][cx0 + 2 + j];
            float d2 = sIn[ci][ry + 2][cx0 + 2 + j];
            acc2[j] += a0 * wc[0] + c0 * wc[1] + d0 * wc[2]
                     + aa1 * wc[3] + c1 * wc[4] + d1 * wc[5]
                     + a2 * wc[6] + c2 * wc[7] + d2 * wc[8];
            a0 = c0; aa1 = c1; a2 = c2;
            c0 = d0; c1 = d1; c2 = d2;
        }
    }
    float* aggp = g_agg + row * 4096 + o * 1024 + ry * 32 + cx0;
    #pragma unroll
    for (int j = 0; j < 16; ++j)
        atomicAdd(aggp + j, fmaxf(acc2[j], 0.f));
}

// ---------------------------------------------------------------------------
// 3) transposed-conv upsample (unchanged)
// ---------------------------------------------------------------------------
__global__ __launch_bounds__(256) void k_up(const float* __restrict__ w,
                                            const float* __restrict__ b) {
    int idx = blockIdx.x * 256 + threadIdx.x;
    int n   = idx >> 14;
    int rem = idx & 16383;
    int o   = rem >> 12;
    int p   = rem & 4095;
    int y   = p >> 6;
    int xq  = p & 63;
    int i = y >> 1, j = xq >> 1, a = y & 1, bb = xq & 1;
    float v = __ldg(b + o);
    const float* ag = g_agg + n * 4096 + i * 32 + j;
    #pragma unroll
    for (int c = 0; c < 4; ++c)
        v += ag[c * 1024] * __ldg(w + (((c * 4 + o) * 2 + a) * 2 + bb));
    g_up[idx] = v;
}

// ---------------------------------------------------------------------------
// 4/5) direct 3x3 SAME conv via packed FFMA2.
//   Block: (32,4) = 128 threads, covers 8 rows x 32 cols x OCB out-channels.
//   blockIdx.y = (oblk << 3) | ytile.
//   SMEM: pre-packed weight pairs [OCB/2][CIN][9][2] + double-buffered tile.
//   Each thread: 8 rows x 4 channel-pairs = 32 f32x2 accumulators.
// ---------------------------------------------------------------------------
template <int CIN, int COUT, int OCB, bool RELU, bool CONCAT>
__global__ __launch_bounds__(128, 2)
void k_conv3x3(const float* __restrict__ in, const float* __restrict__ in2,
               const float* __restrict__ w, const float* __restrict__ bias,
               float* __restrict__ out) {
    extern __shared__ float sm[];
    float* sW = sm;                              // (OCB/2)*CIN*9*2 floats
    float* sT = sm + (OCB / 2) * CIN * 18;       // 2 x 344 floats

    const int n    = blockIdx.z;
    const int oblk = blockIdx.y >> 3;
    const int ty0  = (blockIdx.y & 7) * 8;
    const int tx0  = blockIdx.x * 32;
    const int tx   = threadIdx.x;                // 0..31
    const int og   = threadIdx.y;                // 0..3
    const int tid  = og * 32 + tx;

    // ---- copy + interleave weights for this block's OCB output channels ----
    const float* wg = w + (size_t)oblk * OCB * CIN * 9;
    for (int i = tid; i < OCB * CIN * 9; i += 128) {
        int o = i / (CIN * 9);
        int r = i - o * (CIN * 9);               // c*9 + t
        sW[((o >> 1) * (CIN * 9) + r) * 2 + (o & 1)] = __ldg(wg + i);
    }

    // ---- per-thread tile-load metadata (fixed across channels) ----
    constexpr int NLD = (340 + 127) / 128;       // 3
    int goff[NLD], soff[NLD];
    #pragma unroll
    for (int j = 0; j < NLD; ++j) {
        int i = tid + j * 128;
        if (i < 340) {
            int sy = i / 34, sx = i - sy * 34;
            int gy = ty0 + sy - 1, gx = tx0 + sx - 1;
            soff[j] = i;
            goff[j] = ((unsigned)gy < 64u && (unsigned)gx < 64u) ? gy * 64 + gx : -1;
        } else { soff[j] = -1; goff[j] = -1; }
    }

    // ---- init accumulators with packed bias ----
    ull acc[8][4];
    #pragma unroll
    for (int p = 0; p < 4; ++p) {
        int oc = oblk * OCB + og * 8 + 2 * p;
        ull bp = pk2(__ldg(bias + oc), __ldg(bias + oc + 1));
        #pragma unroll
        for (int r = 0; r < 8; ++r) acc[r][p] = bp;
    }

    // ---- prologue: stage channel 0 ----
    {
        const float* s;
        if (CONCAT) s = in + (size_t)n * 32 * 4096;           // c = 0 < 32
        else        s = in + (size_t)n * CIN * 4096;
        #pragma unroll
        for (int j = 0; j < NLD; ++j)
            if (soff[j] >= 0) sT[soff[j]] = (goff[j] >= 0) ? __ldg(s + goff[j]) : 0.f;
    }
    __syncthreads();

    // ---- main channel loop: 1 barrier / channel, dbl-buffered ----
    for (int c = 0; c < CIN; ++c) {
        const float* sbuf = sT + (c & 1) * 344;

        // prefetch channel c+1 into registers
        float pf[NLD];
        if (c + 1 < CIN) {
            const float* s;
            int cn = c + 1;
            if (CONCAT) s = (cn < 32) ? in  + ((size_t)n * 32 + cn) * 4096
                                      : in2 + ((size_t)n * 4 + (cn - 32)) * 4096;
            else        s = in + ((size_t)n * CIN + cn) * 4096;
            #pragma unroll
            for (int j = 0; j < NLD; ++j)
                pf[j] = (goff[j] >= 0) ? __ldg(s + goff[j]) : 0.f;
        }

        // weight pairs for this channel (ull units; pair stride = CIN*9)
        const ull* wp = reinterpret_cast<const ull*>(sW) + (og * 4) * (CIN * 9) + c * 9;

        #pragma unroll
        for (int dx = 0; dx < 3; ++dx) {
            ull vp[10];
            #pragma unroll
            for (int y = 0; y < 10; ++y) {
                float v = sbuf[y * 34 + tx + dx];
                vp[y] = pk2(v, v);
            }
            #pragma unroll
            for (int dy = 0; dy < 3; ++dy) {
                const int t = dy * 3 + dx;
                ull w0 = wp[0 * (CIN * 9) + t];
                ull w1 = wp[1 * (CIN * 9) + t];
                ull w2 = wp[2 * (CIN * 9) + t];
                ull w3 = wp[3 * (CIN * 9) + t];
                #pragma unroll
                for (int r = 0; r < 8; ++r) {
                    fma2(acc[r][0], vp[r + dy], w0);
                    fma2(acc[r][1], vp[r + dy], w1);
                    fma2(acc[r][2], vp[r + dy], w2);
                    fma2(acc[r][3], vp[r + dy], w3);
                }
            }
        }

        // commit prefetched channel to the other buffer
        if (c + 1 < CIN) {
            float* nb = sT + ((c + 1) & 1) * 344;
            #pragma unroll
            for (int j = 0; j < NLD; ++j)
                if (soff[j] >= 0) nb[soff[j]] = pf[j];
        }
        __syncthreads();
    }

    // ---- epilogue ----
    #pragma unroll
    for (int p = 0; p < 4; ++p) {
        int oc = oblk * OCB + og * 8 + 2 * p;
        float* o0 = out + (((size_t)n * COUT + oc) * 64 + ty0) * 64 + tx0 + tx;
        #pragma unroll
        for (int r = 0; r < 8; ++r) {
            float lo, hi;
            upk2(acc[r][p], lo, hi);
            if (RELU) { lo = fmaxf(lo, 0.f); hi = fmaxf(hi, 0.f); }
            o0[r * 64]        = lo;
            o0[4096 + r * 64] = hi;
        }
    }
}

// ---------------------------------------------------------------------------
extern "C" void kernel_launch(void* const* d_in, const int* in_sizes, int n_in,
                              void* d_out, int out_size) {
    const float* x      = (const float*)d_in[0];
    const int*   eidx   = (const int*)  d_in[1];
    const float* w_down = (const float*)d_in[3];
    const float* b_down = (const float*)d_in[4];
    const float* w_e1   = (const float*)d_in[5];
    const float* b_e1   = (const float*)d_in[6];
    const float* w_e2   = (const float*)d_in[7];
    const float* b_e2   = (const float*)d_in[8];
    const float* w_up   = (const float*)d_in[9];
    const float* b_up   = (const float*)d_in[10];
    const float* w_n1   = (const float*)d_in[11];
    const float* b_n1   = (const float*)d_in[12];
    const float* w_n2   = (const float*)d_in[13];
    const float* b_n2   = (const float*)d_in[14];
    float* out = (float*)d_out;

    float *up_ptr = nullptr, *hid_ptr = nullptr;
    cudaGetSymbolAddress((void**)&up_ptr,  g_up);
    cudaGetSymbolAddress((void**)&hid_ptr, g_hidden);

    // dynamic smem sizes: weights (OCB/2*CIN*9*2) + tile (2*344), floats
    const int sm1 = (16 * 36 * 9 * 2 + 2 * 344) * 4;   // 44224 B
    const int sm2 = (16 * 64 * 9 * 2 + 2 * 344) * 4;   // 76480 B
    cudaFuncSetAttribute((const void*)k_conv3x3<36, 64, 32, true, true>,
                         cudaFuncAttributeMaxDynamicSharedMemorySize, sm1);
    cudaFuncSetAttribute((const void*)k_conv3x3<64, 32, 32, false, false>,
                         cudaFuncAttributeMaxDynamicSharedMemorySize, sm2);

    // 1) downsample (also zeroes g_agg)
    k_down<<<1024, 256>>>(x, w_down, b_down);
    // 2) fused edge network + scatter-add
    k_edge<<<NEDGE, 256>>>(eidx, w_e1, b_e1, w_e2, b_e2);
    // 3) upsample
    k_up<<<16384, 256>>>(w_up, b_up);
    // 4) node conv1: concat(x, up) 36 -> 64, ReLU   (grid.y = 2 oblk * 8 ytiles)
    k_conv3x3<36, 64, 32, true, true><<<dim3(2, 16, 256), dim3(32, 4), sm1>>>(
        x, up_ptr, w_n1, b_n1, hid_ptr);
    // 5) node conv2: 64 -> 32                        (grid.y = 1 oblk * 8 ytiles)
    k_conv3x3<64, 32, 32, false, false><<<dim3(2, 8, 256), dim3(32, 4), sm2>>>(
        hid_ptr, nullptr, w_n2, b_n2, out);
}

// round 5
// speedup vs baseline: 1.5337x; 1.5337x over previous
#include <cuda_runtime.h>
#include <cuda_bf16.h>
#include <cstdint>
#include <cstddef>

#define NNODE 256
#define NEDGE 4096

typedef unsigned long long ull;

// ---------------- device scratch (no runtime allocation allowed) ------------
__device__ float g_xd [NNODE * 4 * 32 * 32];                    //  4 MB
__device__ float g_agg[NNODE * 4 * 32 * 32];                    //  4 MB
// conv1 input: channel-last bf16 hi/lo, 48-padded: [n][y][x][48]
__device__ __align__(16) __nv_bfloat16 g_in1h[(size_t)NNODE * 4096 * 48];
__device__ __align__(16) __nv_bfloat16 g_in1l[(size_t)NNODE * 4096 * 48];
// hidden: channel-last bf16 hi/lo, 64 ch: [n][y][x][64]
__device__ __align__(16) __nv_bfloat16 g_hidh[(size_t)NNODE * 4096 * 64];
__device__ __align__(16) __nv_bfloat16 g_hidl[(size_t)NNODE * 4096 * 64];
// weights pre-packed in HMMA B-fragment order: [tap][kc][n8][lane][2] u32
__device__ __align__(16) uint32_t g_Bf1h[9 * 3 * 8 * 32 * 2];   // conv1 hi
__device__ __align__(16) uint32_t g_Bf1l[9 * 3 * 8 * 32 * 2];   // conv1 lo
__device__ __align__(16) uint32_t g_Bf2h[9 * 4 * 4 * 32 * 2];   // conv2 hi
__device__ __align__(16) uint32_t g_Bf2l[9 * 4 * 4 * 32 * 2];   // conv2 lo

// ---------------- helpers ---------------------------------------------------
__device__ __forceinline__ uint32_t smem_u32(const void* p) {
    uint32_t a;
    asm("{ .reg .u64 t; cvta.to.shared.u64 t, %1; cvt.u32.u64 %0, t; }"
        : "=r"(a) : "l"(p));
    return a;
}
__device__ __forceinline__ void ldmx4(uint32_t* r, uint32_t addr) {
    asm volatile("ldmatrix.sync.aligned.m8n8.x4.shared.b16 {%0,%1,%2,%3}, [%4];"
                 : "=r"(r[0]), "=r"(r[1]), "=r"(r[2]), "=r"(r[3]) : "r"(addr));
}
__device__ __forceinline__ void mma16816(float* d, const uint32_t* a, uint2 b) {
    asm volatile("mma.sync.aligned.m16n8k16.row.col.f32.bf16.bf16.f32 "
                 "{%0,%1,%2,%3},{%4,%5,%6,%7},{%8,%9},{%0,%1,%2,%3};"
                 : "+f"(d[0]), "+f"(d[1]), "+f"(d[2]), "+f"(d[3])
                 : "r"(a[0]), "r"(a[1]), "r"(a[2]), "r"(a[3]), "r"(b.x), "r"(b.y));
}
__device__ __forceinline__ void bsplit(float v, __nv_bfloat16& h, __nv_bfloat16& l) {
    h = __float2bfloat16(v);
    l = __float2bfloat16(v - __bfloat162float(h));
}
__device__ __forceinline__ uint32_t pkbf(__nv_bfloat16 a, __nv_bfloat16 b) {
    __nv_bfloat162 t(a, b);
    return *reinterpret_cast<uint32_t*>(&t);
}

// ---------------------------------------------------------------------------
// 1) downsample + zero g_agg (validated R1)
// ---------------------------------------------------------------------------
__global__ __launch_bounds__(256) void k_down(const float* __restrict__ x,
                                              const float* __restrict__ w,
                                              const float* __restrict__ b) {
    int idx = blockIdx.x * 256 + threadIdx.x;
    int n = idx >> 10, p = (idx >> 5) & 31, q = idx & 31;
    float a0 = __ldg(b + 0), a1 = __ldg(b + 1), a2 = __ldg(b + 2), a3 = __ldg(b + 3);
    const float* xp = x + (size_t)n * 32 * 4096 + (2 * p) * 64 + 2 * q;
    #pragma unroll 4
    for (int c = 0; c < 32; ++c) {
        const float* r0 = xp + c * 4096;
        float v00 = r0[0], v01 = r0[1], v10 = r0[64], v11 = r0[65];
        const float* wp = w + (c << 2);
        a0 += v00 * __ldg(wp +   0) + v01 * __ldg(wp +   1) + v10 * __ldg(wp +   2) + v11 * __ldg(wp +   3);
        a1 += v00 * __ldg(wp + 128) + v01 * __ldg(wp + 129) + v10 * __ldg(wp + 130) + v11 * __ldg(wp + 131);
        a2 += v00 * __ldg(wp + 256) + v01 * __ldg(wp + 257) + v10 * __ldg(wp + 258) + v11 * __ldg(wp + 259);
        a3 += v00 * __ldg(wp + 384) + v01 * __ldg(wp + 385) + v10 * __ldg(wp + 386) + v11 * __ldg(wp + 387);
    }
    float* op = g_xd + n * 4096 + p * 32 + q;
    op[0] = a0; op[1024] = a1; op[2048] = a2; op[3072] = a3;
    float* ap = g_agg + n * 4096 + p * 32 + q;
    ap[0] = 0.f; ap[1024] = 0.f; ap[2048] = 0.f; ap[3072] = 0.f;
}

// ---------------------------------------------------------------------------
// 2) fused edge network + scatter (validated R1)
// ---------------------------------------------------------------------------
__global__ __launch_bounds__(256, 1) void k_edge(const int* __restrict__ eidx,
                                                 const float* __restrict__ we1,
                                                 const float* __restrict__ be1,
                                                 const float* __restrict__ we2,
                                                 const float* __restrict__ be2) {
    __shared__ float sIn[8][34][34];
    const int e = blockIdx.x;
    const int row = eidx[e];
    const int col = eidx[NEDGE + e];
    const int tid = threadIdx.x;
    float* sflat = &sIn[0][0][0];
    for (int i = tid; i < 8 * 34 * 34; i += 256) sflat[i] = 0.f;
    __syncthreads();
    for (int i = tid; i < 8192; i += 256) {
        int ch = i >> 10, p = i & 1023;
        int node = (ch < 4) ? row : col;
        sIn[ch][(p >> 5) + 1][(p & 31) + 1] = g_xd[node * 4096 + (ch & 3) * 1024 + p];
    }
    __syncthreads();
    const int o = tid >> 6, lane = tid & 63;
    const int ry = lane >> 1, cx0 = (lane & 1) << 4;

    float w1[72];
    #pragma unroll
    for (int i = 0; i < 72; ++i) w1[i] = __ldg(we1 + o * 72 + i);
    float acc1[16];
    { float bv = __ldg(be1 + o);
      #pragma unroll
      for (int j = 0; j < 16; ++j) acc1[j] = bv; }
    #pragma unroll
    for (int ci = 0; ci < 8; ++ci) {
        float a0 = sIn[ci][ry][cx0],     aa1 = sIn[ci][ry + 1][cx0],     a2 = sIn[ci][ry + 2][cx0];
        float c0 = sIn[ci][ry][cx0 + 1], c1 = sIn[ci][ry + 1][cx0 + 1],  c2 = sIn[ci][ry + 2][cx0 + 1];
        const float* wc = w1 + ci * 9;
        #pragma unroll
        for (int j = 0; j < 16; ++j) {
            float d0 = sIn[ci][ry][cx0 + 2 + j], d1 = sIn[ci][ry + 1][cx0 + 2 + j], d2 = sIn[ci][ry + 2][cx0 + 2 + j];
            acc1[j] += a0 * wc[0] + c0 * wc[1] + d0 * wc[2] + aa1 * wc[3] + c1 * wc[4] + d1 * wc[5]
                     + a2 * wc[6] + c2 * wc[7] + d2 * wc[8];
            a0 = c0; aa1 = c1; a2 = c2; c0 = d0; c1 = d1; c2 = d2;
        }
    }
    __syncthreads();
    #pragma unroll
    for (int j = 0; j < 16; ++j) sIn[o][ry + 1][cx0 + 1 + j] = fmaxf(acc1[j], 0.f);
    __syncthreads();

    float w2[36];
    #pragma unroll
    for (int i = 0; i < 36; ++i) w2[i] = __ldg(we2 + o * 36 + i);
    float acc2[16];
    { float bv = __ldg(be2 + o);
      #pragma unroll
      for (int j = 0; j < 16; ++j) acc2[j] = bv; }
    #pragma unroll
    for (int ci = 0; ci < 4; ++ci) {
        float a0 = sIn[ci][ry][cx0],     aa1 = sIn[ci][ry + 1][cx0],     a2 = sIn[ci][ry + 2][cx0];
        float c0 = sIn[ci][ry][cx0 + 1], c1 = sIn[ci][ry + 1][cx0 + 1],  c2 = sIn[ci][ry + 2][cx0 + 1];
        const float* wc = w2 + ci * 9;
        #pragma unroll
        for (int j = 0; j < 16; ++j) {
            float d0 = sIn[ci][ry][cx0 + 2 + j], d1 = sIn[ci][ry + 1][cx0 + 2 + j], d2 = sIn[ci][ry + 2][cx0 + 2 + j];
            acc2[j] += a0 * wc[0] + c0 * wc[1] + d0 * wc[2] + aa1 * wc[3] + c1 * wc[4] + d1 * wc[5]
                     + a2 * wc[6] + c2 * wc[7] + d2 * wc[8];
            a0 = c0; aa1 = c1; a2 = c2; c0 = d0; c1 = d1; c2 = d2;
        }
    }
    float* aggp = g_agg + row * 4096 + o * 1024 + ry * 32 + cx0;
    #pragma unroll
    for (int j = 0; j < 16; ++j) atomicAdd(aggp + j, fmaxf(acc2[j], 0.f));
}

// ---------------------------------------------------------------------------
// 3) weight prep: split hi/lo, pack into HMMA B-fragment order.
//    frag u32 index i = ((t*KC + kc)*N8 + n8)*64 + lane*2 + r
//    value: bf16x2 of W[o][c0], W[o][c0+1]; o = n8*8 + lane>>2;
//    c0 = kc*16 + (lane&3)*2 + r*8
// ---------------------------------------------------------------------------
__global__ __launch_bounds__(256) void k_wprep(const float* __restrict__ w1,
                                               const float* __restrict__ w2) {
    int i = blockIdx.x * 256 + threadIdx.x;
    if (i < 13824) {                                    // conv1: 9*3*8*64
        int t = i / 1536, rem = i % 1536;
        int kc = rem / 512, rem2 = rem % 512;
        int n8 = rem2 / 64, rem3 = rem2 % 64;
        int lane = rem3 >> 1, r = rem3 & 1;
        int o  = n8 * 8 + (lane >> 2);
        int c0 = kc * 16 + ((lane & 3) << 1) + r * 8;
        float v0 = (c0     < 36) ? __ldg(w1 + (size_t)(o * 36 + c0)     * 9 + t) : 0.f;
        float v1 = (c0 + 1 < 36) ? __ldg(w1 + (size_t)(o * 36 + c0 + 1) * 9 + t) : 0.f;
        __nv_bfloat16 h0, l0, h1, l1;
        bsplit(v0, h0, l0); bsplit(v1, h1, l1);
        g_Bf1h[i] = pkbf(h0, h1);
        g_Bf1l[i] = pkbf(l0, l1);
    } else if (i < 13824 + 9216) {                      // conv2: 9*4*4*64
        int j = i - 13824;
        int t = j / 1024, rem = j % 1024;
        int kc = rem / 256, rem2 = rem % 256;
        int n8 = rem2 / 64, rem3 = rem2 % 64;
        int lane = rem3 >> 1, r = rem3 & 1;
        int o  = n8 * 8 + (lane >> 2);
        int c0 = kc * 16 + ((lane & 3) << 1) + r * 8;
        float v0 = __ldg(w2 + (size_t)(o * 64 + c0)     * 9 + t);
        float v1 = __ldg(w2 + (size_t)(o * 64 + c0 + 1) * 9 + t);
        __nv_bfloat16 h0, l0, h1, l1;
        bsplit(v0, h0, l0); bsplit(v1, h1, l1);
        g_Bf2h[j] = pkbf(h0, h1);
        g_Bf2l[j] = pkbf(l0, l1);
    }
}

// ---------------------------------------------------------------------------
// 4) conv1 input prep: fused upsample + concat + channel-last bf16 split.
//    g_in1{h,l}[n][y][x][48]: ch 0..31 = x, 32..35 = up(agg), 36..47 = 0
// ---------------------------------------------------------------------------
__global__ __launch_bounds__(256) void k_prep1(const float* __restrict__ x,
                                               const float* __restrict__ wup,
                                               const float* __restrict__ bup) {
    int idx = blockIdx.x * 256 + threadIdx.x;     // N*4096 pixels
    int n = idx >> 12, p = idx & 4095, y = p >> 6, xx = p & 63;
    int i = y >> 1, j = xx >> 1, a = y & 1, b = xx & 1;
    const float* ag = g_agg + n * 4096 + i * 32 + j;
    float up[4];
    #pragma unroll
    for (int o = 0; o < 4; ++o) {
        float v = __ldg(bup + o);
        #pragma unroll
        for (int c = 0; c < 4; ++c)
            v += ag[c * 1024] * __ldg(wup + (((c * 4 + o) * 2 + a) * 2 + b));
        up[o] = v;
    }
    uint32_t ph[24], pl[24];
    const float* xp = x + (size_t)n * 32 * 4096 + p;
    #pragma unroll
    for (int c2 = 0; c2 < 16; ++c2) {
        __nv_bfloat16 h0, l0, h1, l1;
        bsplit(__ldg(xp + (2 * c2) * 4096), h0, l0);
        bsplit(__ldg(xp + (2 * c2 + 1) * 4096), h1, l1);
        ph[c2] = pkbf(h0, h1); pl[c2] = pkbf(l0, l1);
    }
    #pragma unroll
    for (int c2 = 16; c2 < 18; ++c2) {
        __nv_bfloat16 h0, l0, h1, l1;
        bsplit(up[2 * (c2 - 16)], h0, l0);
        bsplit(up[2 * (c2 - 16) + 1], h1, l1);
        ph[c2] = pkbf(h0, h1); pl[c2] = pkbf(l0, l1);
    }
    #pragma unroll
    for (int c2 = 18; c2 < 24; ++c2) { ph[c2] = 0u; pl[c2] = 0u; }
    uint4* oh = reinterpret_cast<uint4*>(g_in1h) + (size_t)idx * 6;
    uint4* ol = reinterpret_cast<uint4*>(g_in1l) + (size_t)idx * 6;
    #pragma unroll
    for (int u = 0; u < 6; ++u) {
        oh[u] = make_uint4(ph[4 * u], ph[4 * u + 1], ph[4 * u + 2], ph[4 * u + 3]);
        ol[u] = make_uint4(pl[4 * u], pl[4 * u + 1], pl[4 * u + 2], pl[4 * u + 3]);
    }
}

// ---------------------------------------------------------------------------
// 5) warp-MMA implicit-GEMM 3x3 conv (bf16 3-product split, fp32 acc).
//    CTA = 128 threads = 4 warps; tile = 128 pixels (2 rows x 64 cols) x COUT.
//    smem: halo window [4][66][WS] bf16, hi then lo; staged once.
//    A frags: ldmatrix.x4 from shifted window addresses (9 taps).
//    B frags: direct LDG.64 from pre-packed fragment arrays (L1/L2 broadcast).
// ---------------------------------------------------------------------------
template <int CPAD, int WS, int N8, int KC, bool CONV1>
__global__ __launch_bounds__(128)
void k_conv_wmma(const uint4* __restrict__ inh, const uint4* __restrict__ inl,
                 const uint2* __restrict__ bfh, const uint2* __restrict__ bfl,
                 const float* __restrict__ bias, float* __restrict__ out32) {
    extern __shared__ __align__(16) char smw[];
    constexpr int WPIX   = 4 * 66;
    constexpr int WBYTES = WPIX * WS * 2;
    __nv_bfloat16* winh = (__nv_bfloat16*)smw;
    __nv_bfloat16* winl = (__nv_bfloat16*)(smw + WBYTES);

    const int tid = threadIdx.x;
    const int n  = blockIdx.x >> 5;
    const int y0 = (blockIdx.x & 31) << 1;

    // ---- stage halo window (hi + lo), zero-padded borders ----
    constexpr int NV = CPAD / 8;                  // uint4 per pixel
    for (int i = tid; i < WPIX; i += 128) {
        int wy = i / 66, wx = i - wy * 66;
        int gy = y0 + wy - 1, gx = wx - 1;
        uint4* dh = (uint4*)(winh + i * WS);
        uint4* dl = (uint4*)(winl + i * WS);
        if ((unsigned)gy < 64u && (unsigned)gx < 64u) {
            size_t s = ((size_t)(n * 64 + gy) * 64 + gx) * NV;
            #pragma unroll
            for (int u = 0; u < NV; ++u) { dh[u] = __ldg(inh + s + u); dl[u] = __ldg(inl + s + u); }
        } else {
            uint4 z = make_uint4(0, 0, 0, 0);
            #pragma unroll
            for (int u = 0; u < NV; ++u) { dh[u] = z; dl[u] = z; }
        }
    }
    __syncthreads();

    const int w = tid >> 5, lane = tid & 31;
    // ldmatrix lane geometry: tile t4 = lane>>3; tiles {0,1} = k-low m{0-7,8-15},
    // tiles {2,3} = k-high. Row-in-tile = lane&7.
    const int t4 = lane >> 3, rowin = lane & 7;
    const int mloc = ((t4 & 1) << 3) + rowin;
    const uint32_t kbyte = (uint32_t)(t4 >> 1) * 16;     // +8 channels for k-high tiles
    const uint32_t wbh = smem_u32(winh);
    uint32_t baseA[2];
    #pragma unroll
    for (int mb = 0; mb < 2; ++mb) {
        int p = w * 32 + mb * 16 + mloc;
        int ry = p >> 6, xx = p & 63;
        baseA[mb] = wbh + (uint32_t)(ry * 66 + xx) * (WS * 2) + kbyte;
    }
    constexpr uint32_t WLO = (uint32_t)WBYTES;

    // ---- accumulators pre-loaded with bias ----
    const int cb = (lane & 3) << 1;               // channel pair base within n8
    float acc[2][N8][4];
    #pragma unroll
    for (int n8 = 0; n8 < N8; ++n8) {
        float b0 = __ldg(bias + n8 * 8 + cb);
        float b1 = __ldg(bias + n8 * 8 + cb + 1);
        #pragma unroll
        for (int mb = 0; mb < 2; ++mb) {
            acc[mb][n8][0] = b0; acc[mb][n8][1] = b1;
            acc[mb][n8][2] = b0; acc[mb][n8][3] = b1;
        }
    }

    // ---- main loop: 9 taps x KC k16-chunks ----
    for (int t = 0; t < 9; ++t) {
        const int dy = t / 3, dx = t - dy * 3;
        const uint32_t tapoff = (uint32_t)(dy * 66 + dx) * (WS * 2);
        #pragma unroll
        for (int kc = 0; kc < KC; ++kc) {
            uint32_t ah[2][4], al[2][4];
            #pragma unroll
            for (int mb = 0; mb < 2; ++mb) {
                uint32_t ad = baseA[mb] + tapoff + (uint32_t)kc * 32;
                ldmx4(ah[mb], ad);
                ldmx4(al[mb], ad + WLO);
            }
            const size_t fb = (size_t)((t * KC + kc) * N8) * 32 + lane;
            #pragma unroll
            for (int n8 = 0; n8 < N8; ++n8) {
                uint2 bh = __ldg(bfh + fb + n8 * 32);
                uint2 bl = __ldg(bfl + fb + n8 * 32);
                #pragma unroll
                for (int mb = 0; mb < 2; ++mb) {
                    mma16816(acc[mb][n8], ah[mb], bh);
                    mma16816(acc[mb][n8], ah[mb], bl);
                    mma16816(acc[mb][n8], al[mb], bh);
                }
            }
        }
    }

    // ---- epilogue ----
    #pragma unroll
    for (int mb = 0; mb < 2; ++mb) {
        #pragma unroll
        for (int half = 0; half < 2; ++half) {
            int m  = w * 32 + mb * 16 + (lane >> 2) + half * 8;
            int oy = y0 + (m >> 6), ox = m & 63;
            size_t pix = ((size_t)(n * 64 + oy) * 64 + ox);
            if (CONV1) {
                uint32_t* oh = reinterpret_cast<uint32_t*>(g_hidh) + pix * 32 + (cb >> 1);
                uint32_t* ol = reinterpret_cast<uint32_t*>(g_hidl) + pix * 32 + (cb >> 1);
                #pragma unroll
                for (int n8 = 0; n8 < N8; ++n8) {
                    float v0 = fmaxf(acc[mb][n8][half * 2 + 0], 0.f);
                    float v1 = fmaxf(acc[mb][n8][half * 2 + 1], 0.f);
                    __nv_bfloat16 h0, l0, h1, l1;
                    bsplit(v0, h0, l0); bsplit(v1, h1, l1);
                    oh[n8 * 4] = pkbf(h0, h1);
                    ol[n8 * 4] = pkbf(l0, l1);
                }
            } else {
                float* ob = out32 + (size_t)n * 32 * 4096 + (size_t)oy * 64 + ox;
                #pragma unroll
                for (int n8 = 0; n8 < N8; ++n8) {
                    int ch = n8 * 8 + cb;
                    ob[(size_t)ch * 4096]       = acc[mb][n8][half * 2 + 0];
                    ob[(size_t)(ch + 1) * 4096] = acc[mb][n8][half * 2 + 1];
                }
            }
        }
    }
}

// ---------------------------------------------------------------------------
extern "C" void kernel_launch(void* const* d_in, const int* in_sizes, int n_in,
                              void* d_out, int out_size) {
    const float* x      = (const float*)d_in[0];
    const int*   eidx   = (const int*)  d_in[1];
    const float* w_down = (const float*)d_in[3];
    const float* b_down = (const float*)d_in[4];
    const float* w_e1   = (const float*)d_in[5];
    const float* b_e1   = (const float*)d_in[6];
    const float* w_e2   = (const float*)d_in[7];
    const float* b_e2   = (const float*)d_in[8];
    const float* w_up   = (const float*)d_in[9];
    const float* b_up   = (const float*)d_in[10];
    const float* w_n1   = (const float*)d_in[11];
    const float* b_n1   = (const float*)d_in[12];
    const float* w_n2   = (const float*)d_in[13];
    const float* b_n2   = (const float*)d_in[14];
    float* out = (float*)d_out;

    void *p_in1h, *p_in1l, *p_hidh, *p_hidl, *p_B1h, *p_B1l, *p_B2h, *p_B2l;
    cudaGetSymbolAddress(&p_in1h, g_in1h);
    cudaGetSymbolAddress(&p_in1l, g_in1l);
    cudaGetSymbolAddress(&p_hidh, g_hidh);
    cudaGetSymbolAddress(&p_hidl, g_hidl);
    cudaGetSymbolAddress(&p_B1h, g_Bf1h);
    cudaGetSymbolAddress(&p_B1l, g_Bf1l);
    cudaGetSymbolAddress(&p_B2h, g_Bf2h);
    cudaGetSymbolAddress(&p_B2l, g_Bf2l);

    // dynamic smem: window hi+lo
    const int sm1 = 2 * 4 * 66 * 56 * 2;   // 59136 B (conv1: WS=56)
    const int sm2 = 2 * 4 * 66 * 72 * 2;   // 76032 B (conv2: WS=72)
    cudaFuncSetAttribute((const void*)k_conv_wmma<48, 56, 8, 3, true>,
                         cudaFuncAttributeMaxDynamicSharedMemorySize, sm1);
    cudaFuncSetAttribute((const void*)k_conv_wmma<64, 72, 4, 4, false>,
                         cudaFuncAttributeMaxDynamicSharedMemorySize, sm2);

    // 1) downsample (also zeroes g_agg)
    k_down<<<1024, 256>>>(x, w_down, b_down);
    // 2) weight prep (independent of edge path)
    k_wprep<<<90, 256>>>(w_n1, w_n2);
    // 3) fused edge network + scatter-add
    k_edge<<<NEDGE, 256>>>(eidx, w_e1, b_e1, w_e2, b_e2);
    // 4) conv1 input prep: upsample + concat + bf16 split (channel-last)
    k_prep1<<<4096, 256>>>(x, w_up, b_up);
    // 5) node conv1: 48(pad) -> 64, ReLU, emit split hidden
    k_conv_wmma<48, 56, 8, 3, true><<<8192, 128, sm1>>>(
        (const uint4*)p_in1h, (const uint4*)p_in1l,
        (const uint2*)p_B1h, (const uint2*)p_B1l, b_n1, nullptr);
    // 6) node conv2: 64 -> 32
    k_conv_wmma<64, 72, 4, 4, false><<<8192, 128, sm2>>>(
        (const uint4*)p_hidh, (const uint4*)p_hidl,
        (const uint2*)p_B2h, (const uint2*)p_B2l, b_n2, out);
}

// round 6
// speedup vs baseline: 1.6958x; 1.1056x over previous
#include <cuda_runtime.h>
#include <cuda_bf16.h>
#include <cstdint>
#include <cstddef>

#define NNODE 256
#define NEDGE 4096

// ---------------- device scratch (no runtime allocation allowed) ------------
__device__ float g_xd [NNODE * 4 * 32 * 32];                    //  4 MB
__device__ float g_agg[NNODE * 4 * 32 * 32];                    //  4 MB
// hidden: channel-last bf16 hi/lo, 64 ch: [n][y][x][64]
__device__ __align__(16) __nv_bfloat16 g_hidh[(size_t)NNODE * 4096 * 64];
__device__ __align__(16) __nv_bfloat16 g_hidl[(size_t)NNODE * 4096 * 64];
// weights pre-packed in HMMA B-fragment order: [tap][kc][n8][lane][2] u32
__device__ __align__(16) uint32_t g_Bf1h[9 * 3 * 8 * 32 * 2];   // conv1 hi
__device__ __align__(16) uint32_t g_Bf1l[9 * 3 * 8 * 32 * 2];   // conv1 lo
__device__ __align__(16) uint32_t g_Bf2h[9 * 4 * 4 * 32 * 2];   // conv2 hi
__device__ __align__(16) uint32_t g_Bf2l[9 * 4 * 4 * 32 * 2];   // conv2 lo

// ---------------- helpers ---------------------------------------------------
__device__ __forceinline__ uint32_t smem_u32(const void* p) {
    uint32_t a;
    asm("{ .reg .u64 t; cvta.to.shared.u64 t, %1; cvt.u32.u64 %0, t; }"
        : "=r"(a) : "l"(p));
    return a;
}
__device__ __forceinline__ void ldmx4(uint32_t* r, uint32_t addr) {
    asm volatile("ldmatrix.sync.aligned.m8n8.x4.shared.b16 {%0,%1,%2,%3}, [%4];"
                 : "=r"(r[0]), "=r"(r[1]), "=r"(r[2]), "=r"(r[3]) : "r"(addr));
}
__device__ __forceinline__ void mma16816(float* d, const uint32_t* a, uint2 b) {
    asm volatile("mma.sync.aligned.m16n8k16.row.col.f32.bf16.bf16.f32 "
                 "{%0,%1,%2,%3},{%4,%5,%6,%7},{%8,%9},{%0,%1,%2,%3};"
                 : "+f"(d[0]), "+f"(d[1]), "+f"(d[2]), "+f"(d[3])
                 : "r"(a[0]), "r"(a[1]), "r"(a[2]), "r"(a[3]), "r"(b.x), "r"(b.y));
}
__device__ __forceinline__ void bsplit(float v, __nv_bfloat16& h, __nv_bfloat16& l) {
    h = __float2bfloat16(v);
    l = __float2bfloat16(v - __bfloat162float(h));
}
__device__ __forceinline__ uint32_t pkbf(__nv_bfloat16 a, __nv_bfloat16 b) {
    __nv_bfloat162 t(a, b);
    return *reinterpret_cast<uint32_t*>(&t);
}

// ---------------------------------------------------------------------------
// 1) downsample + zero g_agg (validated R1)
// ---------------------------------------------------------------------------
__global__ __launch_bounds__(256) void k_down(const float* __restrict__ x,
                                              const float* __restrict__ w,
                                              const float* __restrict__ b) {
    int idx = blockIdx.x * 256 + threadIdx.x;
    int n = idx >> 10, p = (idx >> 5) & 31, q = idx & 31;
    float a0 = __ldg(b + 0), a1 = __ldg(b + 1), a2 = __ldg(b + 2), a3 = __ldg(b + 3);
    const float* xp = x + (size_t)n * 32 * 4096 + (2 * p) * 64 + 2 * q;
    #pragma unroll 4
    for (int c = 0; c < 32; ++c) {
        const float* r0 = xp + c * 4096;
        float v00 = r0[0], v01 = r0[1], v10 = r0[64], v11 = r0[65];
        const float* wp = w + (c << 2);
        a0 += v00 * __ldg(wp +   0) + v01 * __ldg(wp +   1) + v10 * __ldg(wp +   2) + v11 * __ldg(wp +   3);
        a1 += v00 * __ldg(wp + 128) + v01 * __ldg(wp + 129) + v10 * __ldg(wp + 130) + v11 * __ldg(wp + 131);
        a2 += v00 * __ldg(wp + 256) + v01 * __ldg(wp + 257) + v10 * __ldg(wp + 258) + v11 * __ldg(wp + 259);
        a3 += v00 * __ldg(wp + 384) + v01 * __ldg(wp + 385) + v10 * __ldg(wp + 386) + v11 * __ldg(wp + 387);
    }
    float* op = g_xd + n * 4096 + p * 32 + q;
    op[0] = a0; op[1024] = a1; op[2048] = a2; op[3072] = a3;
    float* ap = g_agg + n * 4096 + p * 32 + q;
    ap[0] = 0.f; ap[1024] = 0.f; ap[2048] = 0.f; ap[3072] = 0.f;
}

// ---------------------------------------------------------------------------
// 2) fused edge network + scatter (validated R1)
// ---------------------------------------------------------------------------
__global__ __launch_bounds__(256, 1) void k_edge(const int* __restrict__ eidx,
                                                 const float* __restrict__ we1,
                                                 const float* __restrict__ be1,
                                                 const float* __restrict__ we2,
                                                 const float* __restrict__ be2) {
    __shared__ float sIn[8][34][34];
    const int e = blockIdx.x;
    const int row = eidx[e];
    const int col = eidx[NEDGE + e];
    const int tid = threadIdx.x;
    float* sflat = &sIn[0][0][0];
    for (int i = tid; i < 8 * 34 * 34; i += 256) sflat[i] = 0.f;
    __syncthreads();
    for (int i = tid; i < 8192; i += 256) {
        int ch = i >> 10, p = i & 1023;
        int node = (ch < 4) ? row : col;
        sIn[ch][(p >> 5) + 1][(p & 31) + 1] = g_xd[node * 4096 + (ch & 3) * 1024 + p];
    }
    __syncthreads();
    const int o = tid >> 6, lane = tid & 63;
    const int ry = lane >> 1, cx0 = (lane & 1) << 4;

    float w1[72];
    #pragma unroll
    for (int i = 0; i < 72; ++i) w1[i] = __ldg(we1 + o * 72 + i);
    float acc1[16];
    { float bv = __ldg(be1 + o);
      #pragma unroll
      for (int j = 0; j < 16; ++j) acc1[j] = bv; }
    #pragma unroll
    for (int ci = 0; ci < 8; ++ci) {
        float a0 = sIn[ci][ry][cx0],     aa1 = sIn[ci][ry + 1][cx0],     a2 = sIn[ci][ry + 2][cx0];
        float c0 = sIn[ci][ry][cx0 + 1], c1 = sIn[ci][ry + 1][cx0 + 1],  c2 = sIn[ci][ry + 2][cx0 + 1];
        const float* wc = w1 + ci * 9;
        #pragma unroll
        for (int j = 0; j < 16; ++j) {
            float d0 = sIn[ci][ry][cx0 + 2 + j], d1 = sIn[ci][ry + 1][cx0 + 2 + j], d2 = sIn[ci][ry + 2][cx0 + 2 + j];
            acc1[j] += a0 * wc[0] + c0 * wc[1] + d0 * wc[2] + aa1 * wc[3] + c1 * wc[4] + d1 * wc[5]
                     + a2 * wc[6] + c2 * wc[7] + d2 * wc[8];
            a0 = c0; aa1 = c1; a2 = c2; c0 = d0; c1 = d1; c2 = d2;
        }
    }
    __syncthreads();
    #pragma unroll
    for (int j = 0; j < 16; ++j) sIn[o][ry + 1][cx0 + 1 + j] = fmaxf(acc1[j], 0.f);
    __syncthreads();

    float w2[36];
    #pragma unroll
    for (int i = 0; i < 36; ++i) w2[i] = __ldg(we2 + o * 36 + i);
    float acc2[16];
    { float bv = __ldg(be2 + o);
      #pragma unroll
      for (int j = 0; j < 16; ++j) acc2[j] = bv; }
    #pragma unroll
    for (int ci = 0; ci < 4; ++ci) {
        float a0 = sIn[ci][ry][cx0],     aa1 = sIn[ci][ry + 1][cx0],     a2 = sIn[ci][ry + 2][cx0];
        float c0 = sIn[ci][ry][cx0 + 1], c1 = sIn[ci][ry + 1][cx0 + 1],  c2 = sIn[ci][ry + 2][cx0 + 1];
        const float* wc = w2 + ci * 9;
        #pragma unroll
        for (int j = 0; j < 16; ++j) {
            float d0 = sIn[ci][ry][cx0 + 2 + j], d1 = sIn[ci][ry + 1][cx0 + 2 + j], d2 = sIn[ci][ry + 2][cx0 + 2 + j];
            acc2[j] += a0 * wc[0] + c0 * wc[1] + d0 * wc[2] + aa1 * wc[3] + c1 * wc[4] + d1 * wc[5]
                     + a2 * wc[6] + c2 * wc[7] + d2 * wc[8];
            a0 = c0; aa1 = c1; a2 = c2; c0 = d0; c1 = d1; c2 = d2;
        }
    }
    float* aggp = g_agg + row * 4096 + o * 1024 + ry * 32 + cx0;
    #pragma unroll
    for (int j = 0; j < 16; ++j) atomicAdd(aggp + j, fmaxf(acc2[j], 0.f));
}

// ---------------------------------------------------------------------------
// 3) weight prep: split hi/lo, pack into HMMA B-fragment order (validated R5)
// ---------------------------------------------------------------------------
__global__ __launch_bounds__(256) void k_wprep(const float* __restrict__ w1,
                                               const float* __restrict__ w2) {
    int i = blockIdx.x * 256 + threadIdx.x;
    if (i < 13824) {                                    // conv1: 9*3*8*64
        int t = i / 1536, rem = i % 1536;
        int kc = rem / 512, rem2 = rem % 512;
        int n8 = rem2 / 64, rem3 = rem2 % 64;
        int lane = rem3 >> 1, r = rem3 & 1;
        int o  = n8 * 8 + (lane >> 2);
        int c0 = kc * 16 + ((lane & 3) << 1) + r * 8;
        float v0 = (c0     < 36) ? __ldg(w1 + (size_t)(o * 36 + c0)     * 9 + t) : 0.f;
        float v1 = (c0 + 1 < 36) ? __ldg(w1 + (size_t)(o * 36 + c0 + 1) * 9 + t) : 0.f;
        __nv_bfloat16 h0, l0, h1, l1;
        bsplit(v0, h0, l0); bsplit(v1, h1, l1);
        g_Bf1h[i] = pkbf(h0, h1);
        g_Bf1l[i] = pkbf(l0, l1);
    } else if (i < 13824 + 9216) {                      // conv2: 9*4*4*64
        int j = i - 13824;
        int t = j / 1024, rem = j % 1024;
        int kc = rem / 256, rem2 = rem % 256;
        int n8 = rem2 / 64, rem3 = rem2 % 64;
        int lane = rem3 >> 1, r = rem3 & 1;
        int o  = n8 * 8 + (lane >> 2);
        int c0 = kc * 16 + ((lane & 3) << 1) + r * 8;
        float v0 = __ldg(w2 + (size_t)(o * 64 + c0)     * 9 + t);
        float v1 = __ldg(w2 + (size_t)(o * 64 + c0 + 1) * 9 + t);
        __nv_bfloat16 h0, l0, h1, l1;
        bsplit(v0, h0, l0); bsplit(v1, h1, l1);
        g_Bf2h[j] = pkbf(h0, h1);
        g_Bf2l[j] = pkbf(l0, l1);
    }
}

// ---------------------------------------------------------------------------
// 4) conv1: fused staging (x fp32 NCHW + inline upsample + bf16 split) +
//    warp-MMA implicit GEMM. CTA = 256 threads = 8 warps,
//    tile = 4 output rows x 64 cols. Window 6x66 px, WS=56 bf16/pixel.
// ---------------------------------------------------------------------------
__global__ __launch_bounds__(256, 2)
void k_conv1(const float* __restrict__ x,
             const float* __restrict__ wup, const float* __restrict__ bup,
             const uint2* __restrict__ bfh, const uint2* __restrict__ bfl,
             const float* __restrict__ bias) {
    extern __shared__ __align__(16) char smw[];
    constexpr int WS = 56;                        // bf16 per pixel (48 + pad)
    constexpr int WPIX = 6 * 66;
    constexpr int WBYTES = WPIX * WS * 2;         // 44352
    __nv_bfloat16* winh = (__nv_bfloat16*)smw;
    __nv_bfloat16* winl = (__nv_bfloat16*)(smw + WBYTES);

    const int tid = threadIdx.x;
    const int n  = blockIdx.x >> 4;
    const int y0 = (blockIdx.x & 15) << 2;

    // ---- stage halo window: x (32ch) + upsample(agg) (4ch) + 12 zero pad ----
    for (int i = tid; i < WPIX; i += 256) {
        int wy = i / 66, wx = i - wy * 66;
        int gy = y0 + wy - 1, gx = wx - 1;
        uint4* dh = (uint4*)(winh + i * WS);
        uint4* dl = (uint4*)(winl + i * WS);
        if ((unsigned)gy < 64u && (unsigned)gx < 64u) {
            // upsample: up[o] = bup[o] + sum_c agg[n,c,gy/2,gx/2]*wup[c,o,gy&1,gx&1]
            const float* ag = g_agg + n * 4096 + (gy >> 1) * 32 + (gx >> 1);
            const int ab = ((gy & 1) << 1) + (gx & 1);
            float up[4];
            #pragma unroll
            for (int o = 0; o < 4; ++o) {
                float v = __ldg(bup + o);
                #pragma unroll
                for (int c = 0; c < 4; ++c)
                    v += ag[c * 1024] * __ldg(wup + ((c * 4 + o) << 2) + ab);
                up[o] = v;
            }
            uint32_t ph[24], pl[24];
            const float* xp = x + (size_t)n * 32 * 4096 + gy * 64 + gx;
            #pragma unroll
            for (int c2 = 0; c2 < 16; ++c2) {
                __nv_bfloat16 h0, l0, h1, l1;
                bsplit(__ldg(xp + (2 * c2) * 4096), h0, l0);
                bsplit(__ldg(xp + (2 * c2 + 1) * 4096), h1, l1);
                ph[c2] = pkbf(h0, h1); pl[c2] = pkbf(l0, l1);
            }
            #pragma unroll
            for (int c2 = 16; c2 < 18; ++c2) {
                __nv_bfloat16 h0, l0, h1, l1;
                bsplit(up[2 * (c2 - 16)], h0, l0);
                bsplit(up[2 * (c2 - 16) + 1], h1, l1);
                ph[c2] = pkbf(h0, h1); pl[c2] = pkbf(l0, l1);
            }
            #pragma unroll
            for (int c2 = 18; c2 < 24; ++c2) { ph[c2] = 0u; pl[c2] = 0u; }
            #pragma unroll
            for (int u = 0; u < 6; ++u) {
                dh[u] = make_uint4(ph[4 * u], ph[4 * u + 1], ph[4 * u + 2], ph[4 * u + 3]);
                dl[u] = make_uint4(pl[4 * u], pl[4 * u + 1], pl[4 * u + 2], pl[4 * u + 3]);
            }
        } else {
            uint4 z = make_uint4(0, 0, 0, 0);
            #pragma unroll
            for (int u = 0; u < 6; ++u) { dh[u] = z; dl[u] = z; }
        }
    }
    __syncthreads();

    // ---- MMA phase: warp w owns row rw = w>>1, cols colbase = (w&1)*32 ----
    const int w = tid >> 5, lane = tid & 31;
    const int rw = w >> 1, colbase = (w & 1) << 5;
    const int t4 = lane >> 3, rowin = lane & 7;
    const int mloc = ((t4 & 1) << 3) + rowin;
    const uint32_t kbyte = (uint32_t)(t4 >> 1) * 16;
    const uint32_t wbh = smem_u32(winh);
    uint32_t baseA[2];
    #pragma unroll
    for (int mb = 0; mb < 2; ++mb) {
        int xx = colbase + mb * 16 + mloc;
        baseA[mb] = wbh + (uint32_t)(rw * 66 + xx) * (WS * 2) + kbyte;
    }
    constexpr uint32_t WLO = (uint32_t)WBYTES;

    const int cb = (lane & 3) << 1;
    float acc[2][8][4];
    #pragma unroll
    for (int n8 = 0; n8 < 8; ++n8) {
        float b0 = __ldg(bias + n8 * 8 + cb);
        float b1 = __ldg(bias + n8 * 8 + cb + 1);
        #pragma unroll
        for (int mb = 0; mb < 2; ++mb) {
            acc[mb][n8][0] = b0; acc[mb][n8][1] = b1;
            acc[mb][n8][2] = b0; acc[mb][n8][3] = b1;
        }
    }

    for (int t = 0; t < 9; ++t) {
        const int dy = t / 3, dx = t - dy * 3;
        const uint32_t tapoff = (uint32_t)(dy * 66 + dx) * (WS * 2);
        #pragma unroll
        for (int kc = 0; kc < 3; ++kc) {
            uint32_t ah[2][4], al[2][4];
            #pragma unroll
            for (int mb = 0; mb < 2; ++mb) {
                uint32_t ad = baseA[mb] + tapoff + (uint32_t)kc * 32;
                ldmx4(ah[mb], ad);
                ldmx4(al[mb], ad + WLO);
            }
            const size_t fb = (size_t)((t * 3 + kc) * 8) * 32 + lane;
            #pragma unroll
            for (int n8 = 0; n8 < 8; ++n8) {
                uint2 bh = __ldg(bfh + fb + n8 * 32);
                uint2 bl = __ldg(bfl + fb + n8 * 32);
                #pragma unroll
                for (int mb = 0; mb < 2; ++mb) {
                    mma16816(acc[mb][n8], ah[mb], bh);
                    mma16816(acc[mb][n8], ah[mb], bl);
                    mma16816(acc[mb][n8], al[mb], bh);
                }
            }
        }
    }

    // ---- epilogue: ReLU + bf16 split, channel-last hidden ----
    #pragma unroll
    for (int mb = 0; mb < 2; ++mb) {
        #pragma unroll
        for (int half = 0; half < 2; ++half) {
            int ox = colbase + mb * 16 + (lane >> 2) + half * 8;
            int oy = y0 + rw;
            size_t pix = ((size_t)(n * 64 + oy) * 64 + ox);
            uint32_t* oh = reinterpret_cast<uint32_t*>(g_hidh) + pix * 32 + (cb >> 1);
            uint32_t* ol = reinterpret_cast<uint32_t*>(g_hidl) + pix * 32 + (cb >> 1);
            #pragma unroll
            for (int n8 = 0; n8 < 8; ++n8) {
                float v0 = fmaxf(acc[mb][n8][half * 2 + 0], 0.f);
                float v1 = fmaxf(acc[mb][n8][half * 2 + 1], 0.f);
                __nv_bfloat16 h0, l0, h1, l1;
                bsplit(v0, h0, l0); bsplit(v1, h1, l1);
                oh[n8 * 4] = pkbf(h0, h1);
                ol[n8 * 4] = pkbf(l0, l1);
            }
        }
    }
}

// ---------------------------------------------------------------------------
// 5) conv2: warp-MMA implicit GEMM (validated R5). CTA = 4 warps,
//    tile = 2 rows x 64 cols, window 4x66, WS=72.
// ---------------------------------------------------------------------------
__global__ __launch_bounds__(128)
void k_conv2(const uint4* __restrict__ inh, const uint4* __restrict__ inl,
             const uint2* __restrict__ bfh, const uint2* __restrict__ bfl,
             const float* __restrict__ bias, float* __restrict__ out32) {
    extern __shared__ __align__(16) char smw[];
    constexpr int WS = 72;
    constexpr int WPIX = 4 * 66;
    constexpr int WBYTES = WPIX * WS * 2;
    __nv_bfloat16* winh = (__nv_bfloat16*)smw;
    __nv_bfloat16* winl = (__nv_bfloat16*)(smw + WBYTES);

    const int tid = threadIdx.x;
    const int n  = blockIdx.x >> 5;
    const int y0 = (blockIdx.x & 31) << 1;

    for (int i = tid; i < WPIX; i += 128) {
        int wy = i / 66, wx = i - wy * 66;
        int gy = y0 + wy - 1, gx = wx - 1;
        uint4* dh = (uint4*)(winh + i * WS);
        uint4* dl = (uint4*)(winl + i * WS);
        if ((unsigned)gy < 64u && (unsigned)gx < 64u) {
            size_t s = ((size_t)(n * 64 + gy) * 64 + gx) * 8;
            #pragma unroll
            for (int u = 0; u < 8; ++u) { dh[u] = __ldg(inh + s + u); dl[u] = __ldg(inl + s + u); }
        } else {
            uint4 z = make_uint4(0, 0, 0, 0);
            #pragma unroll
            for (int u = 0; u < 8; ++u) { dh[u] = z; dl[u] = z; }
        }
    }
    __syncthreads();

    const int w = tid >> 5, lane = tid & 31;
    const int t4 = lane >> 3, rowin = lane & 7;
    const int mloc = ((t4 & 1) << 3) + rowin;
    const uint32_t kbyte = (uint32_t)(t4 >> 1) * 16;
    const uint32_t wbh = smem_u32(winh);
    uint32_t baseA[2];
    #pragma unroll
    for (int mb = 0; mb < 2; ++mb) {
        int p = w * 32 + mb * 16 + mloc;
        int ry = p >> 6, xx = p & 63;
        baseA[mb] = wbh + (uint32_t)(ry * 66 + xx) * (WS * 2) + kbyte;
    }
    constexpr uint32_t WLO = (uint32_t)WBYTES;

    const int cb = (lane & 3) << 1;
    float acc[2][4][4];
    #pragma unroll
    for (int n8 = 0; n8 < 4; ++n8) {
        float b0 = __ldg(bias + n8 * 8 + cb);
        float b1 = __ldg(bias + n8 * 8 + cb + 1);
        #pragma unroll
        for (int mb = 0; mb < 2; ++mb) {
            acc[mb][n8][0] = b0; acc[mb][n8][1] = b1;
            acc[mb][n8][2] = b0; acc[mb][n8][3] = b1;
        }
    }

    for (int t = 0; t < 9; ++t) {
        const int dy = t / 3, dx = t - dy * 3;
        const uint32_t tapoff = (uint32_t)(dy * 66 + dx) * (WS * 2);
        #pragma unroll
        for (int kc = 0; kc < 4; ++kc) {
            uint32_t ah[2][4], al[2][4];
            #pragma unroll
            for (int mb = 0; mb < 2; ++mb) {
                uint32_t ad = baseA[mb] + tapoff + (uint32_t)kc * 32;
                ldmx4(ah[mb], ad);
                ldmx4(al[mb], ad + WLO);
            }
            const size_t fb = (size_t)((t * 4 + kc) * 4) * 32 + lane;
            #pragma unroll
            for (int n8 = 0; n8 < 4; ++n8) {
                uint2 bh = __ldg(bfh + fb + n8 * 32);
                uint2 bl = __ldg(bfl + fb + n8 * 32);
                #pragma unroll
                for (int mb = 0; mb < 2; ++mb) {
                    mma16816(acc[mb][n8], ah[mb], bh);
                    mma16816(acc[mb][n8], ah[mb], bl);
                    mma16816(acc[mb][n8], al[mb], bh);
                }
            }
        }
    }

    #pragma unroll
    for (int mb = 0; mb < 2; ++mb) {
        #pragma unroll
        for (int half = 0; half < 2; ++half) {
            int m  = w * 32 + mb * 16 + (lane >> 2) + half * 8;
            int oy = y0 + (m >> 6), ox = m & 63;
            float* ob = out32 + (size_t)n * 32 * 4096 + (size_t)oy * 64 + ox;
            #pragma unroll
            for (int n8 = 0; n8 < 4; ++n8) {
                int ch = n8 * 8 + cb;
                ob[(size_t)ch * 4096]       = acc[mb][n8][half * 2 + 0];
                ob[(size_t)(ch + 1) * 4096] = acc[mb][n8][half * 2 + 1];
            }
        }
    }
}

// ---------------------------------------------------------------------------
extern "C" void kernel_launch(void* const* d_in, const int* in_sizes, int n_in,
                              void* d_out, int out_size) {
    const float* x      = (const float*)d_in[0];
    const int*   eidx   = (const int*)  d_in[1];
    const float* w_down = (const float*)d_in[3];
    const float* b_down = (const float*)d_in[4];
    const float* w_e1   = (const float*)d_in[5];
    const float* b_e1   = (const float*)d_in[6];
    const float* w_e2   = (const float*)d_in[7];
    const float* b_e2   = (const float*)d_in[8];
    const float* w_up   = (const float*)d_in[9];
    const float* b_up   = (const float*)d_in[10];
    const float* w_n1   = (const float*)d_in[11];
    const float* b_n1   = (const float*)d_in[12];
    const float* w_n2   = (const float*)d_in[13];
    const float* b_n2   = (const float*)d_in[14];
    float* out = (float*)d_out;

    void *p_hidh, *p_hidl, *p_B1h, *p_B1l, *p_B2h, *p_B2l;
    cudaGetSymbolAddress(&p_hidh, g_hidh);
    cudaGetSymbolAddress(&p_hidl, g_hidl);
    cudaGetSymbolAddress(&p_B1h, g_Bf1h);
    cudaGetSymbolAddress(&p_B1l, g_Bf1l);
    cudaGetSymbolAddress(&p_B2h, g_Bf2h);
    cudaGetSymbolAddress(&p_B2l, g_Bf2l);

    const int sm1 = 2 * 6 * 66 * 56 * 2;   // 88704 B (conv1 window hi+lo)
    const int sm2 = 2 * 4 * 66 * 72 * 2;   // 76032 B (conv2 window hi+lo)
    cudaFuncSetAttribute((const void*)k_conv1,
                         cudaFuncAttributeMaxDynamicSharedMemorySize, sm1);
    cudaFuncSetAttribute((const void*)k_conv2,
                         cudaFuncAttributeMaxDynamicSharedMemorySize, sm2);

    // 1) downsample (also zeroes g_agg)
    k_down<<<1024, 256>>>(x, w_down, b_down);
    // 2) weight prep (independent)
    k_wprep<<<90, 256>>>(w_n1, w_n2);
    // 3) fused edge network + scatter-add
    k_edge<<<NEDGE, 256>>>(eidx, w_e1, b_e1, w_e2, b_e2);
    // 4) conv1: fused upsample+concat+split staging, 48(pad)->64, ReLU
    k_conv1<<<4096, 256, sm1>>>(x, w_up, b_up,
        (const uint2*)p_B1h, (const uint2*)p_B1l, b_n1);
    // 5) conv2: 64 -> 32
    k_conv2<<<8192, 128, sm2>>>(
        (const uint4*)p_hidh, (const uint4*)p_hidl,
        (const uint2*)p_B2h, (const uint2*)p_B2l, b_n2, out);
}

// round 7
// speedup vs baseline: 1.9653x; 1.1589x over previous
#include <cuda_runtime.h>
#include <cuda_bf16.h>
#include <cstdint>
#include <cstddef>

#define NNODE 256
#define NEDGE 4096

typedef unsigned long long ull;

// ---------------- device scratch (no runtime allocation allowed) ------------
__device__ float g_xd [NNODE * 4 * 32 * 32];                    //  4 MB
__device__ float g_agg[NNODE * 4 * 32 * 32];                    //  4 MB
// hidden: channel-last bf16 hi/lo, 64 ch: [n][y][x][64]
__device__ __align__(16) __nv_bfloat16 g_hidh[(size_t)NNODE * 4096 * 64];
__device__ __align__(16) __nv_bfloat16 g_hidl[(size_t)NNODE * 4096 * 64];
// conv1 weights: k16 part [tap][kc<2][n8<8][lane][2] u32, k8 tail [tap][n8][lane] u32
__device__ __align__(16) uint32_t g_Bf1h [9 * 2 * 8 * 32 * 2];
__device__ __align__(16) uint32_t g_Bf1l [9 * 2 * 8 * 32 * 2];
__device__ __align__(16) uint32_t g_Bf18h[9 * 8 * 32];
__device__ __align__(16) uint32_t g_Bf18l[9 * 8 * 32];
// conv2 weights: [tap][kc<4][n8<4][lane][2] u32
__device__ __align__(16) uint32_t g_Bf2h[9 * 4 * 4 * 32 * 2];
__device__ __align__(16) uint32_t g_Bf2l[9 * 4 * 4 * 32 * 2];

// ---------------- helpers ---------------------------------------------------
__device__ __forceinline__ uint32_t smem_u32(const void* p) {
    uint32_t a;
    asm("{ .reg .u64 t; cvta.to.shared.u64 t, %1; cvt.u32.u64 %0, t; }"
        : "=r"(a) : "l"(p));
    return a;
}
__device__ __forceinline__ void ldmx4(uint32_t* r, uint32_t addr) {
    asm volatile("ldmatrix.sync.aligned.m8n8.x4.shared.b16 {%0,%1,%2,%3}, [%4];"
                 : "=r"(r[0]), "=r"(r[1]), "=r"(r[2]), "=r"(r[3]) : "r"(addr));
}
__device__ __forceinline__ void ldmx2(uint32_t* r, uint32_t addr) {
    asm volatile("ldmatrix.sync.aligned.m8n8.x2.shared.b16 {%0,%1}, [%2];"
                 : "=r"(r[0]), "=r"(r[1]) : "r"(addr));
}
__device__ __forceinline__ void mma16816(float* d, const uint32_t* a, uint2 b) {
    asm volatile("mma.sync.aligned.m16n8k16.row.col.f32.bf16.bf16.f32 "
                 "{%0,%1,%2,%3},{%4,%5,%6,%7},{%8,%9},{%0,%1,%2,%3};"
                 : "+f"(d[0]), "+f"(d[1]), "+f"(d[2]), "+f"(d[3])
                 : "r"(a[0]), "r"(a[1]), "r"(a[2]), "r"(a[3]), "r"(b.x), "r"(b.y));
}
__device__ __forceinline__ void mma1688(float* d, const uint32_t* a, uint32_t b) {
    asm volatile("mma.sync.aligned.m16n8k8.row.col.f32.bf16.bf16.f32 "
                 "{%0,%1,%2,%3},{%4,%5},{%6},{%0,%1,%2,%3};"
                 : "+f"(d[0]), "+f"(d[1]), "+f"(d[2]), "+f"(d[3])
                 : "r"(a[0]), "r"(a[1]), "r"(b));
}
__device__ __forceinline__ void bsplit(float v, __nv_bfloat16& h, __nv_bfloat16& l) {
    h = __float2bfloat16(v);
    l = __float2bfloat16(v - __bfloat162float(h));
}
__device__ __forceinline__ uint32_t pkbf(__nv_bfloat16 a, __nv_bfloat16 b) {
    __nv_bfloat162 t(a, b);
    return *reinterpret_cast<uint32_t*>(&t);
}
__device__ __forceinline__ ull pk2(float a, float b) {
    ull r; asm("mov.b64 %0, {%1, %2};" : "=l"(r) : "f"(a), "f"(b)); return r;
}
__device__ __forceinline__ void fma2(ull& d, ull a, ull b) {
    asm("fma.rn.f32x2 %0, %1, %2, %0;" : "+l"(d) : "l"(a), "l"(b));
}
__device__ __forceinline__ void upk2(ull v, float& a, float& b) {
    asm("mov.b64 {%0, %1}, %2;" : "=f"(a), "=f"(b) : "l"(v));
}

// ---------------------------------------------------------------------------
// 1) downsample + zero g_agg (validated R1)
// ---------------------------------------------------------------------------
__global__ __launch_bounds__(256) void k_down(const float* __restrict__ x,
                                              const float* __restrict__ w,
                                              const float* __restrict__ b) {
    int idx = blockIdx.x * 256 + threadIdx.x;
    int n = idx >> 10, p = (idx >> 5) & 31, q = idx & 31;
    float a0 = __ldg(b + 0), a1 = __ldg(b + 1), a2 = __ldg(b + 2), a3 = __ldg(b + 3);
    const float* xp = x + (size_t)n * 32 * 4096 + (2 * p) * 64 + 2 * q;
    #pragma unroll 4
    for (int c = 0; c < 32; ++c) {
        const float* r0 = xp + c * 4096;
        float v00 = r0[0], v01 = r0[1], v10 = r0[64], v11 = r0[65];
        const float* wp = w + (c << 2);
        a0 += v00 * __ldg(wp +   0) + v01 * __ldg(wp +   1) + v10 * __ldg(wp +   2) + v11 * __ldg(wp +   3);
        a1 += v00 * __ldg(wp + 128) + v01 * __ldg(wp + 129) + v10 * __ldg(wp + 130) + v11 * __ldg(wp + 131);
        a2 += v00 * __ldg(wp + 256) + v01 * __ldg(wp + 257) + v10 * __ldg(wp + 258) + v11 * __ldg(wp + 259);
        a3 += v00 * __ldg(wp + 384) + v01 * __ldg(wp + 385) + v10 * __ldg(wp + 386) + v11 * __ldg(wp + 387);
    }
    float* op = g_xd + n * 4096 + p * 32 + q;
    op[0] = a0; op[1024] = a1; op[2048] = a2; op[3072] = a3;
    float* ap = g_agg + n * 4096 + p * 32 + q;
    ap[0] = 0.f; ap[1024] = 0.f; ap[2048] = 0.f; ap[3072] = 0.f;
}

// ---------------------------------------------------------------------------
// 2) fused edge network + scatter, FFMA2 version.
//    256 threads: og = tid>>7 owns output-channel pair {2og, 2og+1};
//    unit = tid&127: row ry = unit>>2, col-block cx0 = (unit&3)*8.
// ---------------------------------------------------------------------------
__global__ __launch_bounds__(256) void k_edge(const int* __restrict__ eidx,
                                              const float* __restrict__ we1,
                                              const float* __restrict__ be1,
                                              const float* __restrict__ we2,
                                              const float* __restrict__ be2) {
    __shared__ float sIn[8][34][34];
    const int e = blockIdx.x;
    const int row = eidx[e];
    const int col = eidx[NEDGE + e];
    const int tid = threadIdx.x;
    float* sflat = &sIn[0][0][0];
    for (int i = tid; i < 8 * 34 * 34; i += 256) sflat[i] = 0.f;
    __syncthreads();
    for (int i = tid; i < 8192; i += 256) {
        int ch = i >> 10, p = i & 1023;
        int node = (ch < 4) ? row : col;
        sIn[ch][(p >> 5) + 1][(p & 31) + 1] = g_xd[node * 4096 + (ch & 3) * 1024 + p];
    }
    __syncthreads();

    const int og   = tid >> 7;          // 0,1
    const int unit = tid & 127;
    const int ry   = unit >> 2;         // 0..31
    const int cx0  = (unit & 3) << 3;   // 0,8,16,24
    const int o0 = og * 2, o1 = og * 2 + 1;

    // ---- conv1: 8 -> 4 (pairs), ReLU ----
    ull acc1[8];
    { ull bp = pk2(__ldg(be1 + o0), __ldg(be1 + o1));
      #pragma unroll
      for (int j = 0; j < 8; ++j) acc1[j] = bp; }
    #pragma unroll
    for (int ci = 0; ci < 8; ++ci) {
        ull v[3][10];
        #pragma unroll
        for (int d = 0; d < 3; ++d)
            #pragma unroll
            for (int c = 0; c < 10; ++c) {
                float f = sIn[ci][ry + d][cx0 + c];
                v[d][c] = pk2(f, f);
            }
        #pragma unroll
        for (int t = 0; t < 9; ++t) {
            int dy = t / 3, dx = t - dy * 3;
            ull wp = pk2(__ldg(we1 + o0 * 72 + ci * 9 + t),
                         __ldg(we1 + o1 * 72 + ci * 9 + t));
            #pragma unroll
            for (int j = 0; j < 8; ++j) fma2(acc1[j], v[dy][dx + j], wp);
        }
    }
    __syncthreads();
    #pragma unroll
    for (int j = 0; j < 8; ++j) {
        float a, b; upk2(acc1[j], a, b);
        sIn[o0][ry + 1][cx0 + 1 + j] = fmaxf(a, 0.f);
        sIn[o1][ry + 1][cx0 + 1 + j] = fmaxf(b, 0.f);
    }
    __syncthreads();

    // ---- conv2: 4 -> 4 (pairs), ReLU, scatter-add ----
    ull acc2[8];
    { ull bp = pk2(__ldg(be2 + o0), __ldg(be2 + o1));
      #pragma unroll
      for (int j = 0; j < 8; ++j) acc2[j] = bp; }
    #pragma unroll
    for (int ci = 0; ci < 4; ++ci) {
        ull v[3][10];
        #pragma unroll
        for (int d = 0; d < 3; ++d)
            #pragma unroll
            for (int c = 0; c < 10; ++c) {
                float f = sIn[ci][ry + d][cx0 + c];
                v[d][c] = pk2(f, f);
            }
        #pragma unroll
        for (int t = 0; t < 9; ++t) {
            int dy = t / 3, dx = t - dy * 3;
            ull wp = pk2(__ldg(we2 + o0 * 36 + ci * 9 + t),
                         __ldg(we2 + o1 * 36 + ci * 9 + t));
            #pragma unroll
            for (int j = 0; j < 8; ++j) fma2(acc2[j], v[dy][dx + j], wp);
        }
    }
    float* ag0 = g_agg + row * 4096 + o0 * 1024 + ry * 32 + cx0;
    float* ag1 = g_agg + row * 4096 + o1 * 1024 + ry * 32 + cx0;
    #pragma unroll
    for (int j = 0; j < 8; ++j) {
        float a, b; upk2(acc2[j], a, b);
        atomicAdd(ag0 + j, fmaxf(a, 0.f));
        atomicAdd(ag1 + j, fmaxf(b, 0.f));
    }
}

// ---------------------------------------------------------------------------
// 3) weight prep: split hi/lo, pack into HMMA fragment order.
//    conv1: K per tap = 40 = 2 x k16 (ch 0-31) + 1 x k8 (ch 32-39, 36+ = 0).
// ---------------------------------------------------------------------------
__global__ __launch_bounds__(256) void k_wprep(const float* __restrict__ w1,
                                               const float* __restrict__ w2) {
    int i = blockIdx.x * 256 + threadIdx.x;
    if (i < 9216) {                                     // conv1 k16: 9*2*8*64
        int t = i / 1024, rem = i % 1024;
        int kc = rem >> 9, rem2 = rem & 511;
        int n8 = rem2 >> 6, rem3 = rem2 & 63;
        int lane = rem3 >> 1, r = rem3 & 1;
        int o  = n8 * 8 + (lane >> 2);
        int c0 = kc * 16 + ((lane & 3) << 1) + r * 8;   // < 32: always real
        float v0 = __ldg(w1 + (size_t)(o * 36 + c0)     * 9 + t);
        float v1 = __ldg(w1 + (size_t)(o * 36 + c0 + 1) * 9 + t);
        __nv_bfloat16 h0, l0, h1, l1;
        bsplit(v0, h0, l0); bsplit(v1, h1, l1);
        g_Bf1h[i] = pkbf(h0, h1);
        g_Bf1l[i] = pkbf(l0, l1);
    } else if (i < 9216 + 2304) {                       // conv1 k8: 9*8*32
        int j = i - 9216;
        int t = j / 256, rem = j % 256;
        int n8 = rem >> 5, lane = rem & 31;
        int o  = n8 * 8 + (lane >> 2);
        int c0 = 32 + ((lane & 3) << 1);                // 32,34,36,38
        float v0 = (c0     < 36) ? __ldg(w1 + (size_t)(o * 36 + c0)     * 9 + t) : 0.f;
        float v1 = (c0 + 1 < 36) ? __ldg(w1 + (size_t)(o * 36 + c0 + 1) * 9 + t) : 0.f;
        __nv_bfloat16 h0, l0, h1, l1;
        bsplit(v0, h0, l0); bsplit(v1, h1, l1);
        g_Bf18h[j] = pkbf(h0, h1);
        g_Bf18l[j] = pkbf(l0, l1);
    } else if (i < 9216 + 2304 + 9216) {                // conv2: 9*4*4*64
        int j = i - 9216 - 2304;
        int t = j / 1024, rem = j % 1024;
        int kc = rem / 256, rem2 = rem % 256;
        int n8 = rem2 / 64, rem3 = rem2 % 64;
        int lane = rem3 >> 1, r = rem3 & 1;
        int o  = n8 * 8 + (lane >> 2);
        int c0 = kc * 16 + ((lane & 3) << 1) + r * 8;
        float v0 = __ldg(w2 + (size_t)(o * 64 + c0)     * 9 + t);
        float v1 = __ldg(w2 + (size_t)(o * 64 + c0 + 1) * 9 + t);
        __nv_bfloat16 h0, l0, h1, l1;
        bsplit(v0, h0, l0); bsplit(v1, h1, l1);
        g_Bf2h[j] = pkbf(h0, h1);
        g_Bf2l[j] = pkbf(l0, l1);
    }
}

// ---------------------------------------------------------------------------
// 4) conv1: fused staging (x fp32 NCHW + inline upsample + bf16 split) +
//    warp-MMA implicit GEMM. 256 threads, tile 4 rows x 64 cols.
//    Window 6x66 px, WS=40 bf16/pixel (80 B). K/tap = 2 x k16 + 1 x k8.
// ---------------------------------------------------------------------------
__global__ __launch_bounds__(256, 2)
void k_conv1(const float* __restrict__ x,
             const float* __restrict__ wup, const float* __restrict__ bup,
             const uint2* __restrict__ bfh, const uint2* __restrict__ bfl,
             const uint32_t* __restrict__ bf8h, const uint32_t* __restrict__ bf8l,
             const float* __restrict__ bias) {
    extern __shared__ __align__(16) char smw[];
    constexpr int WS = 40;                        // bf16 per pixel
    constexpr int WPIX = 6 * 66;
    constexpr int WBYTES = WPIX * WS * 2;         // 31680
    __nv_bfloat16* winh = (__nv_bfloat16*)smw;
    __nv_bfloat16* winl = (__nv_bfloat16*)(smw + WBYTES);

    const int tid = threadIdx.x;
    const int n  = blockIdx.x >> 4;
    const int y0 = (blockIdx.x & 15) << 2;

    // ---- stage: x (32ch) + upsample(agg) (4ch) + 4 zero pad = 40 ch ----
    for (int i = tid; i < WPIX; i += 256) {
        int wy = i / 66, wx = i - wy * 66;
        int gy = y0 + wy - 1, gx = wx - 1;
        uint4* dh = (uint4*)(winh + i * WS);
        uint4* dl = (uint4*)(winl + i * WS);
        if ((unsigned)gy < 64u && (unsigned)gx < 64u) {
            const float* ag = g_agg + n * 4096 + (gy >> 1) * 32 + (gx >> 1);
            const int ab = ((gy & 1) << 1) + (gx & 1);
            float up[4];
            #pragma unroll
            for (int o = 0; o < 4; ++o) {
                float v = __ldg(bup + o);
                #pragma unroll
                for (int c = 0; c < 4; ++c)
                    v += ag[c * 1024] * __ldg(wup + ((c * 4 + o) << 2) + ab);
                up[o] = v;
            }
            uint32_t ph[20], pl[20];
            const float* xp = x + (size_t)n * 32 * 4096 + gy * 64 + gx;
            #pragma unroll
            for (int c2 = 0; c2 < 16; ++c2) {
                __nv_bfloat16 h0, l0, h1, l1;
                bsplit(__ldg(xp + (2 * c2) * 4096), h0, l0);
                bsplit(__ldg(xp + (2 * c2 + 1) * 4096), h1, l1);
                ph[c2] = pkbf(h0, h1); pl[c2] = pkbf(l0, l1);
            }
            #pragma unroll
            for (int c2 = 16; c2 < 18; ++c2) {
                __nv_bfloat16 h0, l0, h1, l1;
                bsplit(up[2 * (c2 - 16)], h0, l0);
                bsplit(up[2 * (c2 - 16) + 1], h1, l1);
                ph[c2] = pkbf(h0, h1); pl[c2] = pkbf(l0, l1);
            }
            ph[18] = ph[19] = pl[18] = pl[19] = 0u;
            #pragma unroll
            for (int u = 0; u < 5; ++u) {
                dh[u] = make_uint4(ph[4 * u], ph[4 * u + 1], ph[4 * u + 2], ph[4 * u + 3]);
                dl[u] = make_uint4(pl[4 * u], pl[4 * u + 1], pl[4 * u + 2], pl[4 * u + 3]);
            }
        } else {
            uint4 z = make_uint4(0, 0, 0, 0);
            #pragma unroll
            for (int u = 0; u < 5; ++u) { dh[u] = z; dl[u] = z; }
        }
    }
    __syncthreads();

    // ---- MMA phase ----
    const int w = tid >> 5, lane = tid & 31;
    const int rw = w >> 1, colbase = (w & 1) << 5;
    const int t4 = lane >> 3, rowin = lane & 7;
    const int mloc  = ((t4 & 1) << 3) + rowin;               // x4 geometry
    const int mloc8 = ((lane >> 3) & 1) * 8 + (lane & 7);    // x2 geometry
    const uint32_t kbyte = (uint32_t)(t4 >> 1) * 16;
    const uint32_t wbh = smem_u32(winh);
    uint32_t baseA[2], baseA8[2];
    #pragma unroll
    for (int mb = 0; mb < 2; ++mb) {
        int xx = colbase + mb * 16;
        baseA[mb]  = wbh + (uint32_t)(rw * 66 + xx + mloc)  * (WS * 2) + kbyte;
        baseA8[mb] = wbh + (uint32_t)(rw * 66 + xx + mloc8) * (WS * 2);
    }
    constexpr uint32_t WLO = (uint32_t)WBYTES;

    const int cb = (lane & 3) << 1;
    float acc[2][8][4];
    #pragma unroll
    for (int n8 = 0; n8 < 8; ++n8) {
        float b0 = __ldg(bias + n8 * 8 + cb);
        float b1 = __ldg(bias + n8 * 8 + cb + 1);
        #pragma unroll
        for (int mb = 0; mb < 2; ++mb) {
            acc[mb][n8][0] = b0; acc[mb][n8][1] = b1;
            acc[mb][n8][2] = b0; acc[mb][n8][3] = b1;
        }
    }

    for (int t = 0; t < 9; ++t) {
        const int dy = t / 3, dx = t - dy * 3;
        const uint32_t tapoff = (uint32_t)(dy * 66 + dx) * (WS * 2);
        // k16 chunks (ch 0-31)
        #pragma unroll
        for (int kc = 0; kc < 2; ++kc) {
            uint32_t ah[2][4], al[2][4];
            #pragma unroll
            for (int mb = 0; mb < 2; ++mb) {
                uint32_t ad = baseA[mb] + tapoff + (uint32_t)kc * 32;
                ldmx4(ah[mb], ad);
                ldmx4(al[mb], ad + WLO);
            }
            const size_t fb = (size_t)((t * 2 + kc) * 8) * 32 + lane;
            #pragma unroll
            for (int n8 = 0; n8 < 8; ++n8) {
                uint2 bh = __ldg(bfh + fb + n8 * 32);
                uint2 bl = __ldg(bfl + fb + n8 * 32);
                #pragma unroll
                for (int mb = 0; mb < 2; ++mb) {
                    mma16816(acc[mb][n8], ah[mb], bh);
                    mma16816(acc[mb][n8], ah[mb], bl);
                    mma16816(acc[mb][n8], al[mb], bh);
                }
            }
        }
        // k8 tail (ch 32-39)
        {
            uint32_t ah8[2][2], al8[2][2];
            #pragma unroll
            for (int mb = 0; mb < 2; ++mb) {
                uint32_t ad = baseA8[mb] + tapoff + 64u;
                ldmx2(ah8[mb], ad);
                ldmx2(al8[mb], ad + WLO);
            }
            const size_t fb8 = (size_t)(t * 8) * 32 + lane;
            #pragma unroll
            for (int n8 = 0; n8 < 8; ++n8) {
                uint32_t bh = __ldg(bf8h + fb8 + n8 * 32);
                uint32_t bl = __ldg(bf8l + fb8 + n8 * 32);
                #pragma unroll
                for (int mb = 0; mb < 2; ++mb) {
                    mma1688(acc[mb][n8], ah8[mb], bh);
                    mma1688(acc[mb][n8], ah8[mb], bl);
                    mma1688(acc[mb][n8], al8[mb], bh);
                }
            }
        }
    }

    // ---- epilogue: ReLU + bf16 split, channel-last hidden ----
    #pragma unroll
    for (int mb = 0; mb < 2; ++mb) {
        #pragma unroll
        for (int half = 0; half < 2; ++half) {
            int ox = colbase + mb * 16 + (lane >> 2) + half * 8;
            int oy = y0 + rw;
            size_t pix = ((size_t)(n * 64 + oy) * 64 + ox);
            uint32_t* oh = reinterpret_cast<uint32_t*>(g_hidh) + pix * 32 + (cb >> 1);
            uint32_t* ol = reinterpret_cast<uint32_t*>(g_hidl) + pix * 32 + (cb >> 1);
            #pragma unroll
            for (int n8 = 0; n8 < 8; ++n8) {
                float v0 = fmaxf(acc[mb][n8][half * 2 + 0], 0.f);
                float v1 = fmaxf(acc[mb][n8][half * 2 + 1], 0.f);
                __nv_bfloat16 h0, l0, h1, l1;
                bsplit(v0, h0, l0); bsplit(v1, h1, l1);
                oh[n8 * 4] = pkbf(h0, h1);
                ol[n8 * 4] = pkbf(l0, l1);
            }
        }
    }
}

// ---------------------------------------------------------------------------
// 5) conv2: warp-MMA implicit GEMM, 256 threads, tile 4 rows x 64 cols.
//    Window 6x66 px, WS=72 bf16/pixel. K = 9 taps x 4 k16 chunks.
// ---------------------------------------------------------------------------
__global__ __launch_bounds__(256, 2)
void k_conv2(const uint4* __restrict__ inh, const uint4* __restrict__ inl,
             const uint2* __restrict__ bfh, const uint2* __restrict__ bfl,
             const float* __restrict__ bias, float* __restrict__ out32) {
    extern __shared__ __align__(16) char smw[];
    constexpr int WS = 72;
    constexpr int WPIX = 6 * 66;
    constexpr int WBYTES = WPIX * WS * 2;         // 57024
    __nv_bfloat16* winh = (__nv_bfloat16*)smw;
    __nv_bfloat16* winl = (__nv_bfloat16*)(smw + WBYTES);

    const int tid = threadIdx.x;
    const int n  = blockIdx.x >> 4;
    const int y0 = (blockIdx.x & 15) << 2;

    for (int i = tid; i < WPIX; i += 256) {
        int wy = i / 66, wx = i - wy * 66;
        int gy = y0 + wy - 1, gx = wx - 1;
        uint4* dh = (uint4*)(winh + i * WS);
        uint4* dl = (uint4*)(winl + i * WS);
        if ((unsigned)gy < 64u && (unsigned)gx < 64u) {
            size_t s = ((size_t)(n * 64 + gy) * 64 + gx) * 8;
            #pragma unroll
            for (int u = 0; u < 8; ++u) { dh[u] = __ldg(inh + s + u); dl[u] = __ldg(inl + s + u); }
        } else {
            uint4 z = make_uint4(0, 0, 0, 0);
            #pragma unroll
            for (int u = 0; u < 8; ++u) { dh[u] = z; dl[u] = z; }
        }
    }
    __syncthreads();

    const int w = tid >> 5, lane = tid & 31;
    const int rw = w >> 1, colbase = (w & 1) << 5;
    const int t4 = lane >> 3, rowin = lane & 7;
    const int mloc = ((t4 & 1) << 3) + rowin;
    const uint32_t kbyte = (uint32_t)(t4 >> 1) * 16;
    const uint32_t wbh = smem_u32(winh);
    uint32_t baseA[2];
    #pragma unroll
    for (int mb = 0; mb < 2; ++mb) {
        int xx = colbase + mb * 16 + mloc;
        baseA[mb] = wbh + (uint32_t)(rw * 66 + xx) * (WS * 2) + kbyte;
    }
    constexpr uint32_t WLO = (uint32_t)WBYTES;

    const int cb = (lane & 3) << 1;
    float acc[2][4][4];
    #pragma unroll
    for (int n8 = 0; n8 < 4; ++n8) {
        float b0 = __ldg(bias + n8 * 8 + cb);
        float b1 = __ldg(bias + n8 * 8 + cb + 1);
        #pragma unroll
        for (int mb = 0; mb < 2; ++mb) {
            acc[mb][n8][0] = b0; acc[mb][n8][1] = b1;
            acc[mb][n8][2] = b0; acc[mb][n8][3] = b1;
        }
    }

    for (int t = 0; t < 9; ++t) {
        const int dy = t / 3, dx = t - dy * 3;
        const uint32_t tapoff = (uint32_t)(dy * 66 + dx) * (WS * 2);
        #pragma unroll
        for (int kc = 0; kc < 4; ++kc) {
            uint32_t ah[2][4], al[2][4];
            #pragma unroll
            for (int mb = 0; mb < 2; ++mb) {
                uint32_t ad = baseA[mb] + tapoff + (uint32_t)kc * 32;
                ldmx4(ah[mb], ad);
                ldmx4(al[mb], ad + WLO);
            }
            const size_t fb = (size_t)((t * 4 + kc) * 4) * 32 + lane;
            #pragma unroll
            for (int n8 = 0; n8 < 4; ++n8) {
                uint2 bh = __ldg(bfh + fb + n8 * 32);
                uint2 bl = __ldg(bfl + fb + n8 * 32);
                #pragma unroll
                for (int mb = 0; mb < 2; ++mb) {
                    mma16816(acc[mb][n8], ah[mb], bh);
                    mma16816(acc[mb][n8], ah[mb], bl);
                    mma16816(acc[mb][n8], al[mb], bh);
                }
            }
        }
    }

    #pragma unroll
    for (int mb = 0; mb < 2; ++mb) {
        #pragma unroll
        for (int half = 0; half < 2; ++half) {
            int ox = colbase + mb * 16 + (lane >> 2) + half * 8;
            int oy = y0 + rw;
            float* ob = out32 + (size_t)n * 32 * 4096 + (size_t)oy * 64 + ox;
            #pragma unroll
            for (int n8 = 0; n8 < 4; ++n8) {
                int ch = n8 * 8 + cb;
                ob[(size_t)ch * 4096]       = acc[mb][n8][half * 2 + 0];
                ob[(size_t)(ch + 1) * 4096] = acc[mb][n8][half * 2 + 1];
            }
        }
    }
}

// ---------------------------------------------------------------------------
extern "C" void kernel_launch(void* const* d_in, const int* in_sizes, int n_in,
                              void* d_out, int out_size) {
    const float* x      = (const float*)d_in[0];
    const int*   eidx   = (const int*)  d_in[1];
    const float* w_down = (const float*)d_in[3];
    const float* b_down = (const float*)d_in[4];
    const float* w_e1   = (const float*)d_in[5];
    const float* b_e1   = (const float*)d_in[6];
    const float* w_e2   = (const float*)d_in[7];
    const float* b_e2   = (const float*)d_in[8];
    const float* w_up   = (const float*)d_in[9];
    const float* b_up   = (const float*)d_in[10];
    const float* w_n1   = (const float*)d_in[11];
    const float* b_n1   = (const float*)d_in[12];
    const float* w_n2   = (const float*)d_in[13];
    const float* b_n2   = (const float*)d_in[14];
    float* out = (float*)d_out;

    void *p_hidh, *p_hidl, *p_B1h, *p_B1l, *p_B18h, *p_B18l, *p_B2h, *p_B2l;
    cudaGetSymbolAddress(&p_hidh, g_hidh);
    cudaGetSymbolAddress(&p_hidl, g_hidl);
    cudaGetSymbolAddress(&p_B1h,  g_Bf1h);
    cudaGetSymbolAddress(&p_B1l,  g_Bf1l);
    cudaGetSymbolAddress(&p_B18h, g_Bf18h);
    cudaGetSymbolAddress(&p_B18l, g_Bf18l);
    cudaGetSymbolAddress(&p_B2h,  g_Bf2h);
    cudaGetSymbolAddress(&p_B2l,  g_Bf2l);

    const int sm1 = 2 * 6 * 66 * 40 * 2;   //  63360 B (conv1 window hi+lo)
    const int sm2 = 2 * 6 * 66 * 72 * 2;   // 114048 B (conv2 window hi+lo)
    cudaFuncSetAttribute((const void*)k_conv1,
                         cudaFuncAttributeMaxDynamicSharedMemorySize, sm1);
    cudaFuncSetAttribute((const void*)k_conv2,
                         cudaFuncAttributeMaxDynamicSharedMemorySize, sm2);

    // 1) downsample (also zeroes g_agg)
    k_down<<<1024, 256>>>(x, w_down, b_down);
    // 2) weight prep (independent): 9216 + 2304 + 9216 = 20736 elements
    k_wprep<<<81, 256>>>(w_n1, w_n2);
    // 3) fused edge network + scatter-add (FFMA2)
    k_edge<<<NEDGE, 256>>>(eidx, w_e1, b_e1, w_e2, b_e2);
    // 4) conv1: fused upsample+concat+split staging, K=40/tap, ReLU
    k_conv1<<<4096, 256, sm1>>>(x, w_up, b_up,
        (const uint2*)p_B1h, (const uint2*)p_B1l,
        (const uint32_t*)p_B18h, (const uint32_t*)p_B18l, b_n1);
    // 5) conv2: 64 -> 32, 4-row tiles
    k_conv2<<<4096, 256, sm2>>>(
        (const uint4*)p_hidh, (const uint4*)p_hidl,
        (const uint2*)p_B2h, (const uint2*)p_B2l, b_n2, out);
}

// round 8
// speedup vs baseline: 2.8311x; 1.4406x over previous
#include <cuda_runtime.h>
#include <cuda_bf16.h>
#include <cuda_fp16.h>
#include <cstdint>
#include <cstddef>

#define NNODE 256
#define NEDGE 4096

typedef unsigned long long ull;

// ---------------- device scratch (no runtime allocation allowed) ------------
__device__ float g_xd [NNODE * 4 * 32 * 32];                    //  4 MB
__device__ float g_agg[NNODE * 4 * 32 * 32];                    //  4 MB
// hidden: channel-last SINGLE fp16, 64 ch: [n][y][x][64]
__device__ __align__(16) __half g_hidf[(size_t)NNODE * 4096 * 64];   // 134 MB
// conv1 weights (fp16 hi/lo): k16 part [tap][kc<2][n8<8][lane][2] u32, k8 tail
__device__ __align__(16) uint32_t g_Bf1h [9 * 2 * 8 * 32 * 2];
__device__ __align__(16) uint32_t g_Bf1l [9 * 2 * 8 * 32 * 2];
__device__ __align__(16) uint32_t g_Bf18h[9 * 8 * 32];
__device__ __align__(16) uint32_t g_Bf18l[9 * 8 * 32];
// conv2 weights (fp16 hi/lo): [tap][kc<4][n8<4][lane][2] u32
__device__ __align__(16) uint32_t g_Bf2h[9 * 4 * 4 * 32 * 2];
__device__ __align__(16) uint32_t g_Bf2l[9 * 4 * 4 * 32 * 2];

// ---------------- helpers ---------------------------------------------------
__device__ __forceinline__ uint32_t smem_u32(const void* p) {
    uint32_t a;
    asm("{ .reg .u64 t; cvta.to.shared.u64 t, %1; cvt.u32.u64 %0, t; }"
        : "=r"(a) : "l"(p));
    return a;
}
__device__ __forceinline__ void ldmx4(uint32_t* r, uint32_t addr) {
    asm volatile("ldmatrix.sync.aligned.m8n8.x4.shared.b16 {%0,%1,%2,%3}, [%4];"
                 : "=r"(r[0]), "=r"(r[1]), "=r"(r[2]), "=r"(r[3]) : "r"(addr));
}
__device__ __forceinline__ void ldmx2(uint32_t* r, uint32_t addr) {
    asm volatile("ldmatrix.sync.aligned.m8n8.x2.shared.b16 {%0,%1}, [%2];"
                 : "=r"(r[0]), "=r"(r[1]) : "r"(addr));
}
__device__ __forceinline__ void mma16816f(float* d, const uint32_t* a, uint2 b) {
    asm volatile("mma.sync.aligned.m16n8k16.row.col.f32.f16.f16.f32 "
                 "{%0,%1,%2,%3},{%4,%5,%6,%7},{%8,%9},{%0,%1,%2,%3};"
                 : "+f"(d[0]), "+f"(d[1]), "+f"(d[2]), "+f"(d[3])
                 : "r"(a[0]), "r"(a[1]), "r"(a[2]), "r"(a[3]), "r"(b.x), "r"(b.y));
}
__device__ __forceinline__ void mma1688f(float* d, const uint32_t* a, uint32_t b) {
    asm volatile("mma.sync.aligned.m16n8k8.row.col.f32.f16.f16.f32 "
                 "{%0,%1,%2,%3},{%4,%5},{%6},{%0,%1,%2,%3};"
                 : "+f"(d[0]), "+f"(d[1]), "+f"(d[2]), "+f"(d[3])
                 : "r"(a[0]), "r"(a[1]), "r"(b));
}
// fp16 hi/lo split of an fp32 value (weights; lo may be denormal — TC-exact)
__device__ __forceinline__ void hsplit(float v, __half& h, __half& l) {
    h = __float2half(v);
    l = __float2half(v - __half2float(h));
}
__device__ __forceinline__ uint32_t pkhf(__half a, __half b) {
    __half2 t = __halves2half2(a, b);
    return *reinterpret_cast<uint32_t*>(&t);
}
__device__ __forceinline__ ull pk2(float a, float b) {
    ull r; asm("mov.b64 %0, {%1, %2};" : "=l"(r) : "f"(a), "f"(b)); return r;
}
__device__ __forceinline__ void fma2(ull& d, ull a, ull b) {
    asm("fma.rn.f32x2 %0, %1, %2, %0;" : "+l"(d) : "l"(a), "l"(b));
}
__device__ __forceinline__ void upk2(ull v, float& a, float& b) {
    asm("mov.b64 {%0, %1}, %2;" : "=f"(a), "=f"(b) : "l"(v));
}

// ---------------------------------------------------------------------------
// 1) downsample + zero g_agg (validated R1)
// ---------------------------------------------------------------------------
__global__ __launch_bounds__(256) void k_down(const float* __restrict__ x,
                                              const float* __restrict__ w,
                                              const float* __restrict__ b) {
    int idx = blockIdx.x * 256 + threadIdx.x;
    int n = idx >> 10, p = (idx >> 5) & 31, q = idx & 31;
    float a0 = __ldg(b + 0), a1 = __ldg(b + 1), a2 = __ldg(b + 2), a3 = __ldg(b + 3);
    const float* xp = x + (size_t)n * 32 * 4096 + (2 * p) * 64 + 2 * q;
    #pragma unroll 4
    for (int c = 0; c < 32; ++c) {
        const float* r0 = xp + c * 4096;
        float v00 = r0[0], v01 = r0[1], v10 = r0[64], v11 = r0[65];
        const float* wp = w + (c << 2);
        a0 += v00 * __ldg(wp +   0) + v01 * __ldg(wp +   1) + v10 * __ldg(wp +   2) + v11 * __ldg(wp +   3);
        a1 += v00 * __ldg(wp + 128) + v01 * __ldg(wp + 129) + v10 * __ldg(wp + 130) + v11 * __ldg(wp + 131);
        a2 += v00 * __ldg(wp + 256) + v01 * __ldg(wp + 257) + v10 * __ldg(wp + 258) + v11 * __ldg(wp + 259);
        a3 += v00 * __ldg(wp + 384) + v01 * __ldg(wp + 385) + v10 * __ldg(wp + 386) + v11 * __ldg(wp + 387);
    }
    float* op = g_xd + n * 4096 + p * 32 + q;
    op[0] = a0; op[1024] = a1; op[2048] = a2; op[3072] = a3;
    float* ap = g_agg + n * 4096 + p * 32 + q;
    ap[0] = 0.f; ap[1024] = 0.f; ap[2048] = 0.f; ap[3072] = 0.f;
}

// ---------------------------------------------------------------------------
// 2) fused edge network + scatter, FFMA2 (validated R7)
// ---------------------------------------------------------------------------
__global__ __launch_bounds__(256) void k_edge(const int* __restrict__ eidx,
                                              const float* __restrict__ we1,
                                              const float* __restrict__ be1,
                                              const float* __restrict__ we2,
                                              const float* __restrict__ be2) {
    __shared__ float sIn[8][34][34];
    const int e = blockIdx.x;
    const int row = eidx[e];
    const int col = eidx[NEDGE + e];
    const int tid = threadIdx.x;
    float* sflat = &sIn[0][0][0];
    for (int i = tid; i < 8 * 34 * 34; i += 256) sflat[i] = 0.f;
    __syncthreads();
    for (int i = tid; i < 8192; i += 256) {
        int ch = i >> 10, p = i & 1023;
        int node = (ch < 4) ? row : col;
        sIn[ch][(p >> 5) + 1][(p & 31) + 1] = g_xd[node * 4096 + (ch & 3) * 1024 + p];
    }
    __syncthreads();

    const int og   = tid >> 7;
    const int unit = tid & 127;
    const int ry   = unit >> 2;
    const int cx0  = (unit & 3) << 3;
    const int o0 = og * 2, o1 = og * 2 + 1;

    ull acc1[8];
    { ull bp = pk2(__ldg(be1 + o0), __ldg(be1 + o1));
      #pragma unroll
      for (int j = 0; j < 8; ++j) acc1[j] = bp; }
    #pragma unroll
    for (int ci = 0; ci < 8; ++ci) {
        ull v[3][10];
        #pragma unroll
        for (int d = 0; d < 3; ++d)
            #pragma unroll
            for (int c = 0; c < 10; ++c) {
                float f = sIn[ci][ry + d][cx0 + c];
                v[d][c] = pk2(f, f);
            }
        #pragma unroll
        for (int t = 0; t < 9; ++t) {
            int dy = t / 3, dx = t - dy * 3;
            ull wp = pk2(__ldg(we1 + o0 * 72 + ci * 9 + t),
                         __ldg(we1 + o1 * 72 + ci * 9 + t));
            #pragma unroll
            for (int j = 0; j < 8; ++j) fma2(acc1[j], v[dy][dx + j], wp);
        }
    }
    __syncthreads();
    #pragma unroll
    for (int j = 0; j < 8; ++j) {
        float a, b; upk2(acc1[j], a, b);
        sIn[o0][ry + 1][cx0 + 1 + j] = fmaxf(a, 0.f);
        sIn[o1][ry + 1][cx0 + 1 + j] = fmaxf(b, 0.f);
    }
    __syncthreads();

    ull acc2[8];
    { ull bp = pk2(__ldg(be2 + o0), __ldg(be2 + o1));
      #pragma unroll
      for (int j = 0; j < 8; ++j) acc2[j] = bp; }
    #pragma unroll
    for (int ci = 0; ci < 4; ++ci) {
        ull v[3][10];
        #pragma unroll
        for (int d = 0; d < 3; ++d)
            #pragma unroll
            for (int c = 0; c < 10; ++c) {
                float f = sIn[ci][ry + d][cx0 + c];
                v[d][c] = pk2(f, f);
            }
        #pragma unroll
        for (int t = 0; t < 9; ++t) {
            int dy = t / 3, dx = t - dy * 3;
            ull wp = pk2(__ldg(we2 + o0 * 36 + ci * 9 + t),
                         __ldg(we2 + o1 * 36 + ci * 9 + t));
            #pragma unroll
            for (int j = 0; j < 8; ++j) fma2(acc2[j], v[dy][dx + j], wp);
        }
    }
    float* ag0 = g_agg + row * 4096 + o0 * 1024 + ry * 32 + cx0;
    float* ag1 = g_agg + row * 4096 + o1 * 1024 + ry * 32 + cx0;
    #pragma unroll
    for (int j = 0; j < 8; ++j) {
        float a, b; upk2(acc2[j], a, b);
        atomicAdd(ag0 + j, fmaxf(a, 0.f));
        atomicAdd(ag1 + j, fmaxf(b, 0.f));
    }
}

// ---------------------------------------------------------------------------
// 3) weight prep: fp16 hi/lo split, HMMA fragment order (layout as R7)
// ---------------------------------------------------------------------------
__global__ __launch_bounds__(256) void k_wprep(const float* __restrict__ w1,
                                               const float* __restrict__ w2) {
    int i = blockIdx.x * 256 + threadIdx.x;
    if (i < 9216) {                                     // conv1 k16: 9*2*8*64
        int t = i / 1024, rem = i % 1024;
        int kc = rem >> 9, rem2 = rem & 511;
        int n8 = rem2 >> 6, rem3 = rem2 & 63;
        int lane = rem3 >> 1, r = rem3 & 1;
        int o  = n8 * 8 + (lane >> 2);
        int c0 = kc * 16 + ((lane & 3) << 1) + r * 8;
        float v0 = __ldg(w1 + (size_t)(o * 36 + c0)     * 9 + t);
        float v1 = __ldg(w1 + (size_t)(o * 36 + c0 + 1) * 9 + t);
        __half h0, l0, h1, l1;
        hsplit(v0, h0, l0); hsplit(v1, h1, l1);
        g_Bf1h[i] = pkhf(h0, h1);
        g_Bf1l[i] = pkhf(l0, l1);
    } else if (i < 9216 + 2304) {                       // conv1 k8: 9*8*32
        int j = i - 9216;
        int t = j / 256, rem = j % 256;
        int n8 = rem >> 5, lane = rem & 31;
        int o  = n8 * 8 + (lane >> 2);
        int c0 = 32 + ((lane & 3) << 1);
        float v0 = (c0     < 36) ? __ldg(w1 + (size_t)(o * 36 + c0)     * 9 + t) : 0.f;
        float v1 = (c0 + 1 < 36) ? __ldg(w1 + (size_t)(o * 36 + c0 + 1) * 9 + t) : 0.f;
        __half h0, l0, h1, l1;
        hsplit(v0, h0, l0); hsplit(v1, h1, l1);
        g_Bf18h[j] = pkhf(h0, h1);
        g_Bf18l[j] = pkhf(l0, l1);
    } else if (i < 9216 + 2304 + 9216) {                // conv2: 9*4*4*64
        int j = i - 9216 - 2304;
        int t = j / 1024, rem = j % 1024;
        int kc = rem / 256, rem2 = rem % 256;
        int n8 = rem2 / 64, rem3 = rem2 % 64;
        int lane = rem3 >> 1, r = rem3 & 1;
        int o  = n8 * 8 + (lane >> 2);
        int c0 = kc * 16 + ((lane & 3) << 1) + r * 8;
        float v0 = __ldg(w2 + (size_t)(o * 64 + c0)     * 9 + t);
        float v1 = __ldg(w2 + (size_t)(o * 64 + c0 + 1) * 9 + t);
        __half h0, l0, h1, l1;
        hsplit(v0, h0, l0); hsplit(v1, h1, l1);
        g_Bf2h[j] = pkhf(h0, h1);
        g_Bf2l[j] = pkhf(l0, l1);
    }
}

// ---------------------------------------------------------------------------
// 4) conv1: fused staging (x fp32 + inline upsample -> single fp16) +
//    warp-MMA, 2 products (a * w_hi, a * w_lo). 256 threads, 4 rows x 64 cols.
//    Window 6x66 px, WS=40 fp16/pixel. K/tap = 2 x k16 + 1 x k8.
// ---------------------------------------------------------------------------
__global__ __launch_bounds__(256, 2)
void k_conv1(const float* __restrict__ x,
             const float* __restrict__ wup, const float* __restrict__ bup,
             const uint2* __restrict__ bfh, const uint2* __restrict__ bfl,
             const uint32_t* __restrict__ bf8h, const uint32_t* __restrict__ bf8l,
             const float* __restrict__ bias) {
    extern __shared__ __align__(16) char smw[];
    constexpr int WS = 40;
    constexpr int WPIX = 6 * 66;
    __half* winf = (__half*)smw;

    const int tid = threadIdx.x;
    const int n  = blockIdx.x >> 4;
    const int y0 = (blockIdx.x & 15) << 2;

    // ---- stage: x (32ch) + upsample(agg) (4ch) + 4 zero pad, single fp16 ----
    for (int i = tid; i < WPIX; i += 256) {
        int wy = i / 66, wx = i - wy * 66;
        int gy = y0 + wy - 1, gx = wx - 1;
        uint4* df = (uint4*)(winf + i * WS);
        if ((unsigned)gy < 64u && (unsigned)gx < 64u) {
            const float* ag = g_agg + n * 4096 + (gy >> 1) * 32 + (gx >> 1);
            const int ab = ((gy & 1) << 1) + (gx & 1);
            float up[4];
            #pragma unroll
            for (int o = 0; o < 4; ++o) {
                float v = __ldg(bup + o);
                #pragma unroll
                for (int c = 0; c < 4; ++c)
                    v += ag[c * 1024] * __ldg(wup + ((c * 4 + o) << 2) + ab);
                up[o] = v;
            }
            uint32_t ph[20];
            const float* xp = x + (size_t)n * 32 * 4096 + gy * 64 + gx;
            #pragma unroll
            for (int c2 = 0; c2 < 16; ++c2)
                ph[c2] = pkhf(__float2half(__ldg(xp + (2 * c2) * 4096)),
                              __float2half(__ldg(xp + (2 * c2 + 1) * 4096)));
            ph[16] = pkhf(__float2half(up[0]), __float2half(up[1]));
            ph[17] = pkhf(__float2half(up[2]), __float2half(up[3]));
            ph[18] = ph[19] = 0u;
            #pragma unroll
            for (int u = 0; u < 5; ++u)
                df[u] = make_uint4(ph[4 * u], ph[4 * u + 1], ph[4 * u + 2], ph[4 * u + 3]);
        } else {
            uint4 z = make_uint4(0, 0, 0, 0);
            #pragma unroll
            for (int u = 0; u < 5; ++u) df[u] = z;
        }
    }
    __syncthreads();

    // ---- MMA phase ----
    const int w = tid >> 5, lane = tid & 31;
    const int rw = w >> 1, colbase = (w & 1) << 5;
    const int t4 = lane >> 3, rowin = lane & 7;
    const int mloc  = ((t4 & 1) << 3) + rowin;
    const int mloc8 = ((lane >> 3) & 1) * 8 + (lane & 7);
    const uint32_t kbyte = (uint32_t)(t4 >> 1) * 16;
    const uint32_t wbh = smem_u32(winf);
    uint32_t baseA[2], baseA8[2];
    #pragma unroll
    for (int mb = 0; mb < 2; ++mb) {
        int xx = colbase + mb * 16;
        baseA[mb]  = wbh + (uint32_t)(rw * 66 + xx + mloc)  * (WS * 2) + kbyte;
        baseA8[mb] = wbh + (uint32_t)(rw * 66 + xx + mloc8) * (WS * 2);
    }

    const int cb = (lane & 3) << 1;
    float acc[2][8][4];
    #pragma unroll
    for (int n8 = 0; n8 < 8; ++n8) {
        float b0 = __ldg(bias + n8 * 8 + cb);
        float b1 = __ldg(bias + n8 * 8 + cb + 1);
        #pragma unroll
        for (int mb = 0; mb < 2; ++mb) {
            acc[mb][n8][0] = b0; acc[mb][n8][1] = b1;
            acc[mb][n8][2] = b0; acc[mb][n8][3] = b1;
        }
    }

    for (int t = 0; t < 9; ++t) {
        const int dy = t / 3, dx = t - dy * 3;
        const uint32_t tapoff = (uint32_t)(dy * 66 + dx) * (WS * 2);
        #pragma unroll
        for (int kc = 0; kc < 2; ++kc) {
            uint32_t ah[2][4];
            #pragma unroll
            for (int mb = 0; mb < 2; ++mb)
                ldmx4(ah[mb], baseA[mb] + tapoff + (uint32_t)kc * 32);
            const size_t fb = (size_t)((t * 2 + kc) * 8) * 32 + lane;
            #pragma unroll
            for (int n8 = 0; n8 < 8; ++n8) {
                uint2 bh = __ldg(bfh + fb + n8 * 32);
                uint2 bl = __ldg(bfl + fb + n8 * 32);
                #pragma unroll
                for (int mb = 0; mb < 2; ++mb) {
                    mma16816f(acc[mb][n8], ah[mb], bh);
                    mma16816f(acc[mb][n8], ah[mb], bl);
                }
            }
        }
        {   // k8 tail (ch 32-39)
            uint32_t ah8[2][2];
            #pragma unroll
            for (int mb = 0; mb < 2; ++mb)
                ldmx2(ah8[mb], baseA8[mb] + tapoff + 64u);
            const size_t fb8 = (size_t)(t * 8) * 32 + lane;
            #pragma unroll
            for (int n8 = 0; n8 < 8; ++n8) {
                uint32_t bh = __ldg(bf8h + fb8 + n8 * 32);
                uint32_t bl = __ldg(bf8l + fb8 + n8 * 32);
                #pragma unroll
                for (int mb = 0; mb < 2; ++mb) {
                    mma1688f(acc[mb][n8], ah8[mb], bh);
                    mma1688f(acc[mb][n8], ah8[mb], bl);
                }
            }
        }
    }

    // ---- epilogue: ReLU -> single fp16 hidden, channel-last ----
    #pragma unroll
    for (int mb = 0; mb < 2; ++mb) {
        #pragma unroll
        for (int half = 0; half < 2; ++half) {
            int ox = colbase + mb * 16 + (lane >> 2) + half * 8;
            int oy = y0 + rw;
            size_t pix = ((size_t)(n * 64 + oy) * 64 + ox);
            uint32_t* oh = reinterpret_cast<uint32_t*>(g_hidf) + pix * 32 + (cb >> 1);
            #pragma unroll
            for (int n8 = 0; n8 < 8; ++n8) {
                float v0 = fmaxf(acc[mb][n8][half * 2 + 0], 0.f);
                float v1 = fmaxf(acc[mb][n8][half * 2 + 1], 0.f);
                oh[n8 * 4] = pkhf(__float2half(v0), __float2half(v1));
            }
        }
    }
}

// ---------------------------------------------------------------------------
// 5) conv2: warp-MMA, 2 products, single-fp16 A. 256 threads,
//    tile 4 rows x 64 cols, window 6x66 px, WS=72 fp16/pixel.
// ---------------------------------------------------------------------------
__global__ __launch_bounds__(256, 2)
void k_conv2(const uint4* __restrict__ inf,
             const uint2* __restrict__ bfh, const uint2* __restrict__ bfl,
             const float* __restrict__ bias, float* __restrict__ out32) {
    extern __shared__ __align__(16) char smw[];
    constexpr int WS = 72;
    constexpr int WPIX = 6 * 66;
    __half* winf = (__half*)smw;

    const int tid = threadIdx.x;
    const int n  = blockIdx.x >> 4;
    const int y0 = (blockIdx.x & 15) << 2;

    for (int i = tid; i < WPIX; i += 256) {
        int wy = i / 66, wx = i - wy * 66;
        int gy = y0 + wy - 1, gx = wx - 1;
        uint4* df = (uint4*)(winf + i * WS);
        if ((unsigned)gy < 64u && (unsigned)gx < 64u) {
            size_t s = ((size_t)(n * 64 + gy) * 64 + gx) * 8;
            #pragma unroll
            for (int u = 0; u < 8; ++u) df[u] = __ldg(inf + s + u);
        } else {
            uint4 z = make_uint4(0, 0, 0, 0);
            #pragma unroll
            for (int u = 0; u < 8; ++u) df[u] = z;
        }
    }
    __syncthreads();

    const int w = tid >> 5, lane = tid & 31;
    const int rw = w >> 1, colbase = (w & 1) << 5;
    const int t4 = lane >> 3, rowin = lane & 7;
    const int mloc = ((t4 & 1) << 3) + rowin;
    const uint32_t kbyte = (uint32_t)(t4 >> 1) * 16;
    const uint32_t wbh = smem_u32(winf);
    uint32_t baseA[2];
    #pragma unroll
    for (int mb = 0; mb < 2; ++mb) {
        int xx = colbase + mb * 16 + mloc;
        baseA[mb] = wbh + (uint32_t)(rw * 66 + xx) * (WS * 2) + kbyte;
    }

    const int cb = (lane & 3) << 1;
    float acc[2][4][4];
    #pragma unroll
    for (int n8 = 0; n8 < 4; ++n8) {
        float b0 = __ldg(bias + n8 * 8 + cb);
        float b1 = __ldg(bias + n8 * 8 + cb + 1);
        #pragma unroll
        for (int mb = 0; mb < 2; ++mb) {
            acc[mb][n8][0] = b0; acc[mb][n8][1] = b1;
            acc[mb][n8][2] = b0; acc[mb][n8][3] = b1;
        }
    }

    for (int t = 0; t < 9; ++t) {
        const int dy = t / 3, dx = t - dy * 3;
        const uint32_t tapoff = (uint32_t)(dy * 66 + dx) * (WS * 2);
        #pragma unroll
        for (int kc = 0; kc < 4; ++kc) {
            uint32_t ah[2][4];
            #pragma unroll
            for (int mb = 0; mb < 2; ++mb)
                ldmx4(ah[mb], baseA[mb] + tapoff + (uint32_t)kc * 32);
            const size_t fb = (size_t)((t * 4 + kc) * 4) * 32 + lane;
            #pragma unroll
            for (int n8 = 0; n8 < 4; ++n8) {
                uint2 bh = __ldg(bfh + fb + n8 * 32);
                uint2 bl = __ldg(bfl + fb + n8 * 32);
                #pragma unroll
                for (int mb = 0; mb < 2; ++mb) {
                    mma16816f(acc[mb][n8], ah[mb], bh);
                    mma16816f(acc[mb][n8], ah[mb], bl);
                }
            }
        }
    }

    #pragma unroll
    for (int mb = 0; mb < 2; ++mb) {
        #pragma unroll
        for (int half = 0; half < 2; ++half) {
            int ox = colbase + mb * 16 + (lane >> 2) + half * 8;
            int oy = y0 + rw;
            float* ob = out32 + (size_t)n * 32 * 4096 + (size_t)oy * 64 + ox;
            #pragma unroll
            for (int n8 = 0; n8 < 4; ++n8) {
                int ch = n8 * 8 + cb;
                ob[(size_t)ch * 4096]       = acc[mb][n8][half * 2 + 0];
                ob[(size_t)(ch + 1) * 4096] = acc[mb][n8][half * 2 + 1];
            }
        }
    }
}

// ---------------------------------------------------------------------------
extern "C" void kernel_launch(void* const* d_in, const int* in_sizes, int n_in,
                              void* d_out, int out_size) {
    const float* x      = (const float*)d_in[0];
    const int*   eidx   = (const int*)  d_in[1];
    const float* w_down = (const float*)d_in[3];
    const float* b_down = (const float*)d_in[4];
    const float* w_e1   = (const float*)d_in[5];
    const float* b_e1   = (const float*)d_in[6];
    const float* w_e2   = (const float*)d_in[7];
    const float* b_e2   = (const float*)d_in[8];
    const float* w_up   = (const float*)d_in[9];
    const float* b_up   = (const float*)d_in[10];
    const float* w_n1   = (const float*)d_in[11];
    const float* b_n1   = (const float*)d_in[12];
    const float* w_n2   = (const float*)d_in[13];
    const float* b_n2   = (const float*)d_in[14];
    float* out = (float*)d_out;

    void *p_hidf, *p_B1h, *p_B1l, *p_B18h, *p_B18l, *p_B2h, *p_B2l;
    cudaGetSymbolAddress(&p_hidf, g_hidf);
    cudaGetSymbolAddress(&p_B1h,  g_Bf1h);
    cudaGetSymbolAddress(&p_B1l,  g_Bf1l);
    cudaGetSymbolAddress(&p_B18h, g_Bf18h);
    cudaGetSymbolAddress(&p_B18l, g_Bf18l);
    cudaGetSymbolAddress(&p_B2h,  g_Bf2h);
    cudaGetSymbolAddress(&p_B2l,  g_Bf2l);

    const int sm1 = 6 * 66 * 40 * 2;   // 31680 B (conv1 window, single plane)
    const int sm2 = 6 * 66 * 72 * 2;   // 57024 B (conv2 window, single plane)
    cudaFuncSetAttribute((const void*)k_conv1,
                         cudaFuncAttributeMaxDynamicSharedMemorySize, sm1);
    cudaFuncSetAttribute((const void*)k_conv2,
                         cudaFuncAttributeMaxDynamicSharedMemorySize, sm2);

    // 1) downsample (also zeroes g_agg)
    k_down<<<1024, 256>>>(x, w_down, b_down);
    // 2) weight prep
    k_wprep<<<81, 256>>>(w_n1, w_n2);
    // 3) fused edge network + scatter-add (FFMA2)
    k_edge<<<NEDGE, 256>>>(eidx, w_e1, b_e1, w_e2, b_e2);
    // 4) conv1: 2-product fp16, fused staging, ReLU -> fp16 hidden
    k_conv1<<<4096, 256, sm1>>>(x, w_up, b_up,
        (const uint2*)p_B1h, (const uint2*)p_B1l,
        (const uint32_t*)p_B18h, (const uint32_t*)p_B18l, b_n1);
    // 5) conv2: 2-product fp16, 64 -> 32
    k_conv2<<<4096, 256, sm2>>>((const uint4*)p_hidf,
        (const uint2*)p_B2h, (const uint2*)p_B2l, b_n2, out);
}

// round 9
// speedup vs baseline: 3.7979x; 1.3415x over previous
#include <cuda_runtime.h>
#include <cuda_bf16.h>
#include <cuda_fp16.h>
#include <cstdint>
#include <cstddef>

#define NNODE 256
#define NEDGE 4096

typedef unsigned long long ull;

// ---------------- device scratch (no runtime allocation allowed) ------------
__device__ float g_xd [NNODE * 4 * 32 * 32];                    //  4 MB
__device__ float g_agg[NNODE * 4 * 32 * 32];                    //  4 MB
// hidden: channel-last SINGLE fp16, 64 ch: [n][y][x][64]
__device__ __align__(16) __half g_hidf[(size_t)NNODE * 4096 * 64];   // 134 MB
// single-fp16 weights in HMMA B-fragment order (uint2 per lane)
__device__ __align__(16) uint2 g_Bf1[9 * 2 * 8 * 32];   // conv1 x-part [t][kc<2][n8<8][lane]
__device__ __align__(16) uint2 g_Bfu[3 * 8 * 32];       // conv1 up-part [kc<3][n8<8][lane]
__device__ __align__(16) uint2 g_Bf2[9 * 4 * 4 * 32];   // conv2 [t][kc<4][n8<4][lane]

// ---------------- helpers ---------------------------------------------------
__device__ __forceinline__ uint32_t smem_u32(const void* p) {
    uint32_t a;
    asm("{ .reg .u64 t; cvta.to.shared.u64 t, %1; cvt.u32.u64 %0, t; }"
        : "=r"(a) : "l"(p));
    return a;
}
__device__ __forceinline__ void ldmx4(uint32_t* r, uint32_t addr) {
    asm volatile("ldmatrix.sync.aligned.m8n8.x4.shared.b16 {%0,%1,%2,%3}, [%4];"
                 : "=r"(r[0]), "=r"(r[1]), "=r"(r[2]), "=r"(r[3]) : "r"(addr));
}
__device__ __forceinline__ void mma16816f(float* d, const uint32_t* a, uint2 b) {
    asm volatile("mma.sync.aligned.m16n8k16.row.col.f32.f16.f16.f32 "
                 "{%0,%1,%2,%3},{%4,%5,%6,%7},{%8,%9},{%0,%1,%2,%3};"
                 : "+f"(d[0]), "+f"(d[1]), "+f"(d[2]), "+f"(d[3])
                 : "r"(a[0]), "r"(a[1]), "r"(a[2]), "r"(a[3]), "r"(b.x), "r"(b.y));
}
__device__ __forceinline__ uint32_t pkhf(__half a, __half b) {
    __half2 t = __halves2half2(a, b);
    return *reinterpret_cast<uint32_t*>(&t);
}
__device__ __forceinline__ ull pk2(float a, float b) {
    ull r; asm("mov.b64 %0, {%1, %2};" : "=l"(r) : "f"(a), "f"(b)); return r;
}
__device__ __forceinline__ void fma2(ull& d, ull a, ull b) {
    asm("fma.rn.f32x2 %0, %1, %2, %0;" : "+l"(d) : "l"(a), "l"(b));
}
__device__ __forceinline__ void upk2(ull v, float& a, float& b) {
    asm("mov.b64 {%0, %1}, %2;" : "=f"(a), "=f"(b) : "l"(v));
}

// ---------------------------------------------------------------------------
// 1) downsample + zero g_agg (validated R1)
// ---------------------------------------------------------------------------
__global__ __launch_bounds__(256) void k_down(const float* __restrict__ x,
                                              const float* __restrict__ w,
                                              const float* __restrict__ b) {
    int idx = blockIdx.x * 256 + threadIdx.x;
    int n = idx >> 10, p = (idx >> 5) & 31, q = idx & 31;
    float a0 = __ldg(b + 0), a1 = __ldg(b + 1), a2 = __ldg(b + 2), a3 = __ldg(b + 3);
    const float* xp = x + (size_t)n * 32 * 4096 + (2 * p) * 64 + 2 * q;
    #pragma unroll 4
    for (int c = 0; c < 32; ++c) {
        const float* r0 = xp + c * 4096;
        float v00 = r0[0], v01 = r0[1], v10 = r0[64], v11 = r0[65];
        const float* wp = w + (c << 2);
        a0 += v00 * __ldg(wp +   0) + v01 * __ldg(wp +   1) + v10 * __ldg(wp +   2) + v11 * __ldg(wp +   3);
        a1 += v00 * __ldg(wp + 128) + v01 * __ldg(wp + 129) + v10 * __ldg(wp + 130) + v11 * __ldg(wp + 131);
        a2 += v00 * __ldg(wp + 256) + v01 * __ldg(wp + 257) + v10 * __ldg(wp + 258) + v11 * __ldg(wp + 259);
        a3 += v00 * __ldg(wp + 384) + v01 * __ldg(wp + 385) + v10 * __ldg(wp + 386) + v11 * __ldg(wp + 387);
    }
    float* op = g_xd + n * 4096 + p * 32 + q;
    op[0] = a0; op[1024] = a1; op[2048] = a2; op[3072] = a3;
    float* ap = g_agg + n * 4096 + p * 32 + q;
    ap[0] = 0.f; ap[1024] = 0.f; ap[2048] = 0.f; ap[3072] = 0.f;
}

// ---------------------------------------------------------------------------
// 2) fused edge network + scatter, FFMA2 (validated R7)
// ---------------------------------------------------------------------------
__global__ __launch_bounds__(256) void k_edge(const int* __restrict__ eidx,
                                              const float* __restrict__ we1,
                                              const float* __restrict__ be1,
                                              const float* __restrict__ we2,
                                              const float* __restrict__ be2) {
    __shared__ float sIn[8][34][34];
    const int e = blockIdx.x;
    const int row = eidx[e];
    const int col = eidx[NEDGE + e];
    const int tid = threadIdx.x;
    float* sflat = &sIn[0][0][0];
    for (int i = tid; i < 8 * 34 * 34; i += 256) sflat[i] = 0.f;
    __syncthreads();
    for (int i = tid; i < 8192; i += 256) {
        int ch = i >> 10, p = i & 1023;
        int node = (ch < 4) ? row : col;
        sIn[ch][(p >> 5) + 1][(p & 31) + 1] = g_xd[node * 4096 + (ch & 3) * 1024 + p];
    }
    __syncthreads();

    const int og   = tid >> 7;
    const int unit = tid & 127;
    const int ry   = unit >> 2;
    const int cx0  = (unit & 3) << 3;
    const int o0 = og * 2, o1 = og * 2 + 1;

    ull acc1[8];
    { ull bp = pk2(__ldg(be1 + o0), __ldg(be1 + o1));
      #pragma unroll
      for (int j = 0; j < 8; ++j) acc1[j] = bp; }
    #pragma unroll
    for (int ci = 0; ci < 8; ++ci) {
        ull v[3][10];
        #pragma unroll
        for (int d = 0; d < 3; ++d)
            #pragma unroll
            for (int c = 0; c < 10; ++c) {
                float f = sIn[ci][ry + d][cx0 + c];
                v[d][c] = pk2(f, f);
            }
        #pragma unroll
        for (int t = 0; t < 9; ++t) {
            int dy = t / 3, dx = t - dy * 3;
            ull wp = pk2(__ldg(we1 + o0 * 72 + ci * 9 + t),
                         __ldg(we1 + o1 * 72 + ci * 9 + t));
            #pragma unroll
            for (int j = 0; j < 8; ++j) fma2(acc1[j], v[dy][dx + j], wp);
        }
    }
    __syncthreads();
    #pragma unroll
    for (int j = 0; j < 8; ++j) {
        float a, b; upk2(acc1[j], a, b);
        sIn[o0][ry + 1][cx0 + 1 + j] = fmaxf(a, 0.f);
        sIn[o1][ry + 1][cx0 + 1 + j] = fmaxf(b, 0.f);
    }
    __syncthreads();

    ull acc2[8];
    { ull bp = pk2(__ldg(be2 + o0), __ldg(be2 + o1));
      #pragma unroll
      for (int j = 0; j < 8; ++j) acc2[j] = bp; }
    #pragma unroll
    for (int ci = 0; ci < 4; ++ci) {
        ull v[3][10];
        #pragma unroll
        for (int d = 0; d < 3; ++d)
            #pragma unroll
            for (int c = 0; c < 10; ++c) {
                float f = sIn[ci][ry + d][cx0 + c];
                v[d][c] = pk2(f, f);
            }
        #pragma unroll
        for (int t = 0; t < 9; ++t) {
            int dy = t / 3, dx = t - dy * 3;
            ull wp = pk2(__ldg(we2 + o0 * 36 + ci * 9 + t),
                         __ldg(we2 + o1 * 36 + ci * 9 + t));
            #pragma unroll
            for (int j = 0; j < 8; ++j) fma2(acc2[j], v[dy][dx + j], wp);
        }
    }
    float* ag0 = g_agg + row * 4096 + o0 * 1024 + ry * 32 + cx0;
    float* ag1 = g_agg + row * 4096 + o1 * 1024 + ry * 32 + cx0;
    #pragma unroll
    for (int j = 0; j < 8; ++j) {
        float a, b; upk2(acc2[j], a, b);
        atomicAdd(ag0 + j, fmaxf(a, 0.f));
        atomicAdd(ag1 + j, fmaxf(b, 0.f));
    }
}

// ---------------------------------------------------------------------------
// 3) weight prep: single fp16, HMMA B-fragment order (uint2 per lane).
// ---------------------------------------------------------------------------
__global__ __launch_bounds__(256) void k_wprep(const float* __restrict__ w1,
                                               const float* __restrict__ w2) {
    int i = blockIdx.x * 256 + threadIdx.x;
    if (i < 4608) {                                     // conv1 x-part 9*2*8*32
        int t = i / 512, rem = i % 512;
        int kc = rem >> 8, rem2 = rem & 255;
        int n8 = rem2 >> 5, lane = rem2 & 31;
        int o  = n8 * 8 + (lane >> 2);
        int cb = kc * 16 + ((lane & 3) << 1);
        uint2 b;
        b.x = pkhf(__float2half(__ldg(w1 + (size_t)(o * 36 + cb)     * 9 + t)),
                   __float2half(__ldg(w1 + (size_t)(o * 36 + cb + 1) * 9 + t)));
        b.y = pkhf(__float2half(__ldg(w1 + (size_t)(o * 36 + cb + 8) * 9 + t)),
                   __float2half(__ldg(w1 + (size_t)(o * 36 + cb + 9) * 9 + t)));
        g_Bf1[i] = b;
    } else if (i < 4608 + 768) {                        // conv1 up-part 3*8*32
        int j = i - 4608;
        int kc = j / 256, rem = j % 256;
        int n8 = rem >> 5, lane = rem & 31;
        int o  = n8 * 8 + (lane >> 2);
        int k0 = kc * 16 + ((lane & 3) << 1);
        float v[4];
        #pragma unroll
        for (int q = 0; q < 4; ++q) {
            int k = k0 + (q >> 1) * 8 + (q & 1);        // k0,k0+1,k0+8,k0+9
            v[q] = (k < 36)
                 ? __ldg(w1 + (size_t)(o * 36 + 32 + (k & 3)) * 9 + (k >> 2))
                 : 0.f;
        }
        uint2 b;
        b.x = pkhf(__float2half(v[0]), __float2half(v[1]));
        b.y = pkhf(__float2half(v[2]), __float2half(v[3]));
        g_Bfu[j] = b;
    } else if (i < 4608 + 768 + 4608) {                 // conv2 9*4*4*32
        int j = i - 5376;
        int t = j / 512, rem = j % 512;
        int kc = rem >> 7, rem2 = rem & 127;
        int n8 = rem2 >> 5, lane = rem2 & 31;
        int o  = n8 * 8 + (lane >> 2);
        int cb = kc * 16 + ((lane & 3) << 1);
        uint2 b;
        b.x = pkhf(__float2half(__ldg(w2 + (size_t)(o * 64 + cb)     * 9 + t)),
                   __float2half(__ldg(w2 + (size_t)(o * 64 + cb + 1) * 9 + t)));
        b.y = pkhf(__float2half(__ldg(w2 + (size_t)(o * 64 + cb + 8) * 9 + t)),
                   __float2half(__ldg(w2 + (size_t)(o * 64 + cb + 9) * 9 + t)));
        g_Bf2[j] = b;
    }
}

// ---------------------------------------------------------------------------
// 4) conv1: halo window holds only the 32 x-channels (2 clean k16/tap);
//    the 4 up-channels are im2col'd per OUTPUT pixel into uim[256][56]
//    (k = tap*4+ch, 36 real, rest zero) -> 3 k16 chunks total.
//    Single-product fp16 weights. 256 thr, tile 4 rows x 64 cols.
//    smem: winx 396*80B | winu 396*16B fp32 | uim 256*112B.
// ---------------------------------------------------------------------------
__global__ __launch_bounds__(256, 2)
void k_conv1(const float* __restrict__ x,
             const float* __restrict__ wup, const float* __restrict__ bup,
             const uint2* __restrict__ bf1, const uint2* __restrict__ bfu,
             const float* __restrict__ bias) {
    extern __shared__ __align__(16) char smw[];
    char*  winx = smw;                       // 31680 B
    float* winu = (float*)(smw + 31680);     //  6336 B
    char*  uim  = smw + 38016;               // 28672 B

    const int tid = threadIdx.x;
    const int n  = blockIdx.x >> 4;
    const int y0 = (blockIdx.x & 15) << 2;

    // ---- stage halo: x -> fp16 winx; up(agg) -> fp32 winu ----
    for (int i = tid; i < 396; i += 256) {
        int wy = i / 66, wx = i - wy * 66;
        int gy = y0 + wy - 1, gx = wx - 1;
        uint4*  dx4 = (uint4*)(winx + i * 80);
        float4* du  = (float4*)(winu + i * 4);
        if ((unsigned)gy < 64u && (unsigned)gx < 64u) {
            const float* ag = g_agg + n * 4096 + (gy >> 1) * 32 + (gx >> 1);
            const int ab = ((gy & 1) << 1) + (gx & 1);
            float up[4];
            #pragma unroll
            for (int o = 0; o < 4; ++o) {
                float v = __ldg(bup + o);
                #pragma unroll
                for (int c = 0; c < 4; ++c)
                    v += ag[c * 1024] * __ldg(wup + ((c * 4 + o) << 2) + ab);
                up[o] = v;
            }
            *du = make_float4(up[0], up[1], up[2], up[3]);
            uint32_t ph[16];
            const float* xp = x + (size_t)n * 32 * 4096 + gy * 64 + gx;
            #pragma unroll
            for (int c2 = 0; c2 < 16; ++c2)
                ph[c2] = pkhf(__float2half(__ldg(xp + (2 * c2) * 4096)),
                              __float2half(__ldg(xp + (2 * c2 + 1) * 4096)));
            #pragma unroll
            for (int u = 0; u < 4; ++u)
                dx4[u] = make_uint4(ph[4 * u], ph[4 * u + 1], ph[4 * u + 2], ph[4 * u + 3]);
        } else {
            uint4 z = make_uint4(0, 0, 0, 0);
            #pragma unroll
            for (int u = 0; u < 4; ++u) dx4[u] = z;
            *du = make_float4(0.f, 0.f, 0.f, 0.f);
        }
    }
    __syncthreads();

    // ---- im2col the up channels: uim[px][tap*4+ch] fp16, pads zero ----
    {
        int r = tid >> 6, xx = tid & 63;
        uint32_t arr[28];
        #pragma unroll
        for (int t9 = 0; t9 < 9; ++t9) {
            int dy = t9 / 3, dxp = t9 - dy * 3;
            const float* u4 = winu + ((r + dy) * 66 + xx + dxp) * 4;
            arr[t9 * 2 + 0] = pkhf(__float2half(u4[0]), __float2half(u4[1]));
            arr[t9 * 2 + 1] = pkhf(__float2half(u4[2]), __float2half(u4[3]));
        }
        #pragma unroll
        for (int j = 18; j < 28; ++j) arr[j] = 0u;
        uint4* du = (uint4*)(uim + tid * 112);
        #pragma unroll
        for (int u = 0; u < 7; ++u)
            du[u] = make_uint4(arr[4 * u], arr[4 * u + 1], arr[4 * u + 2], arr[4 * u + 3]);
    }
    __syncthreads();

    // ---- MMA phase ----
    const int w = tid >> 5, lane = tid & 31;
    const int rw = w >> 1, colbase = (w & 1) << 5;
    const int t4 = lane >> 3, rowin = lane & 7;
    const int mloc = ((t4 & 1) << 3) + rowin;
    const uint32_t kbyte = (uint32_t)(t4 >> 1) * 16;
    const uint32_t wbx = smem_u32(winx);
    const uint32_t wbu = smem_u32(uim);
    uint32_t baseA[2], baseU[2];
    #pragma unroll
    for (int mb = 0; mb < 2; ++mb) {
        int c = colbase + mb * 16 + mloc;
        baseA[mb] = wbx + (uint32_t)(rw * 66 + c) * 80 + kbyte;
        baseU[mb] = wbu + (uint32_t)(rw * 64 + c) * 112 + kbyte;
    }

    const int cb = (lane & 3) << 1;
    float acc[2][8][4];
    #pragma unroll
    for (int n8 = 0; n8 < 8; ++n8) {
        float b0 = __ldg(bias + n8 * 8 + cb);
        float b1 = __ldg(bias + n8 * 8 + cb + 1);
        #pragma unroll
        for (int mb = 0; mb < 2; ++mb) {
            acc[mb][n8][0] = b0; acc[mb][n8][1] = b1;
            acc[mb][n8][2] = b0; acc[mb][n8][3] = b1;
        }
    }

    for (int t = 0; t < 9; ++t) {
        const int dy = t / 3, dxp = t - dy * 3;
        const uint32_t tapoff = (uint32_t)(dy * 66 + dxp) * 80;
        #pragma unroll
        for (int kc = 0; kc < 2; ++kc) {
            uint32_t ah[2][4];
            #pragma unroll
            for (int mb = 0; mb < 2; ++mb)
                ldmx4(ah[mb], baseA[mb] + tapoff + (uint32_t)kc * 32);
            const size_t fb = (size_t)((t * 2 + kc) * 8) * 32 + lane;
            #pragma unroll
            for (int n8 = 0; n8 < 8; ++n8) {
                uint2 b = __ldg(bf1 + fb + n8 * 32);
                #pragma unroll
                for (int mb = 0; mb < 2; ++mb)
                    mma16816f(acc[mb][n8], ah[mb], b);
            }
        }
    }
    #pragma unroll
    for (int kc = 0; kc < 3; ++kc) {
        uint32_t ah[2][4];
        #pragma unroll
        for (int mb = 0; mb < 2; ++mb)
            ldmx4(ah[mb], baseU[mb] + (uint32_t)kc * 32);
        const size_t fb = (size_t)(kc * 8) * 32 + lane;
        #pragma unroll
        for (int n8 = 0; n8 < 8; ++n8) {
            uint2 b = __ldg(bfu + fb + n8 * 32);
            #pragma unroll
            for (int mb = 0; mb < 2; ++mb)
                mma16816f(acc[mb][n8], ah[mb], b);
        }
    }

    // ---- epilogue: ReLU -> single fp16 hidden, channel-last ----
    #pragma unroll
    for (int mb = 0; mb < 2; ++mb) {
        #pragma unroll
        for (int half = 0; half < 2; ++half) {
            int ox = colbase + mb * 16 + (lane >> 2) + half * 8;
            int oy = y0 + rw;
            size_t pix = ((size_t)(n * 64 + oy) * 64 + ox);
            uint32_t* oh = reinterpret_cast<uint32_t*>(g_hidf) + pix * 32 + (cb >> 1);
            #pragma unroll
            for (int n8 = 0; n8 < 8; ++n8) {
                float v0 = fmaxf(acc[mb][n8][half * 2 + 0], 0.f);
                float v1 = fmaxf(acc[mb][n8][half * 2 + 1], 0.f);
                oh[n8 * 4] = pkhf(__float2half(v0), __float2half(v1));
            }
        }
    }
}

// ---------------------------------------------------------------------------
// 5) conv2: warp-MMA, single-product fp16. 256 threads, 4 rows x 64 cols,
//    window 6x66 px, WS=72 fp16/pixel.
// ---------------------------------------------------------------------------
__global__ __launch_bounds__(256, 2)
void k_conv2(const uint4* __restrict__ inf,
             const uint2* __restrict__ bf2,
             const float* __restrict__ bias, float* __restrict__ out32) {
    extern __shared__ __align__(16) char smw[];
    constexpr int WS = 72;
    constexpr int WPIX = 6 * 66;
    __half* winf = (__half*)smw;

    const int tid = threadIdx.x;
    const int n  = blockIdx.x >> 4;
    const int y0 = (blockIdx.x & 15) << 2;

    for (int i = tid; i < WPIX; i += 256) {
        int wy = i / 66, wx = i - wy * 66;
        int gy = y0 + wy - 1, gx = wx - 1;
        uint4* df = (uint4*)(winf + i * WS);
        if ((unsigned)gy < 64u && (unsigned)gx < 64u) {
            size_t s = ((size_t)(n * 64 + gy) * 64 + gx) * 8;
            #pragma unroll
            for (int u = 0; u < 8; ++u) df[u] = __ldg(inf + s + u);
        } else {
            uint4 z = make_uint4(0, 0, 0, 0);
            #pragma unroll
            for (int u = 0; u < 8; ++u) df[u] = z;
        }
    }
    __syncthreads();

    const int w = tid >> 5, lane = tid & 31;
    const int rw = w >> 1, colbase = (w & 1) << 5;
    const int t4 = lane >> 3, rowin = lane & 7;
    const int mloc = ((t4 & 1) << 3) + rowin;
    const uint32_t kbyte = (uint32_t)(t4 >> 1) * 16;
    const uint32_t wbh = smem_u32(winf);
    uint32_t baseA[2];
    #pragma unroll
    for (int mb = 0; mb < 2; ++mb) {
        int xx = colbase + mb * 16 + mloc;
        baseA[mb] = wbh + (uint32_t)(rw * 66 + xx) * (WS * 2) + kbyte;
    }

    const int cb = (lane & 3) << 1;
    float acc[2][4][4];
    #pragma unroll
    for (int n8 = 0; n8 < 4; ++n8) {
        float b0 = __ldg(bias + n8 * 8 + cb);
        float b1 = __ldg(bias + n8 * 8 + cb + 1);
        #pragma unroll
        for (int mb = 0; mb < 2; ++mb) {
            acc[mb][n8][0] = b0; acc[mb][n8][1] = b1;
            acc[mb][n8][2] = b0; acc[mb][n8][3] = b1;
        }
    }

    for (int t = 0; t < 9; ++t) {
        const int dy = t / 3, dxp = t - dy * 3;
        const uint32_t tapoff = (uint32_t)(dy * 66 + dxp) * (WS * 2);
        #pragma unroll
        for (int kc = 0; kc < 4; ++kc) {
            uint32_t ah[2][4];
            #pragma unroll
            for (int mb = 0; mb < 2; ++mb)
                ldmx4(ah[mb], baseA[mb] + tapoff + (uint32_t)kc * 32);
            const size_t fb = (size_t)((t * 4 + kc) * 4) * 32 + lane;
            #pragma unroll
            for (int n8 = 0; n8 < 4; ++n8) {
                uint2 b = __ldg(bf2 + fb + n8 * 32);
                #pragma unroll
                for (int mb = 0; mb < 2; ++mb)
                    mma16816f(acc[mb][n8], ah[mb], b);
            }
        }
    }

    #pragma unroll
    for (int mb = 0; mb < 2; ++mb) {
        #pragma unroll
        for (int half = 0; half < 2; ++half) {
            int ox = colbase + mb * 16 + (lane >> 2) + half * 8;
            int oy = y0 + rw;
            float* ob = out32 + (size_t)n * 32 * 4096 + (size_t)oy * 64 + ox;
            #pragma unroll
            for (int n8 = 0; n8 < 4; ++n8) {
                int ch = n8 * 8 + cb;
                ob[(size_t)ch * 4096]       = acc[mb][n8][half * 2 + 0];
                ob[(size_t)(ch + 1) * 4096] = acc[mb][n8][half * 2 + 1];
            }
        }
    }
}

// ---------------------------------------------------------------------------
extern "C" void kernel_launch(void* const* d_in, const int* in_sizes, int n_in,
                              void* d_out, int out_size) {
    const float* x      = (const float*)d_in[0];
    const int*   eidx   = (const int*)  d_in[1];
    const float* w_down = (const float*)d_in[3];
    const float* b_down = (const float*)d_in[4];
    const float* w_e1   = (const float*)d_in[5];
    const float* b_e1   = (const float*)d_in[6];
    const float* w_e2   = (const float*)d_in[7];
    const float* b_e2   = (const float*)d_in[8];
    const float* w_up   = (const float*)d_in[9];
    const float* b_up   = (const float*)d_in[10];
    const float* w_n1   = (const float*)d_in[11];
    const float* b_n1   = (const float*)d_in[12];
    const float* w_n2   = (const float*)d_in[13];
    const float* b_n2   = (const float*)d_in[14];
    float* out = (float*)d_out;

    void *p_hidf, *p_B1, *p_Bu, *p_B2;
    cudaGetSymbolAddress(&p_hidf, g_hidf);
    cudaGetSymbolAddress(&p_B1, g_Bf1);
    cudaGetSymbolAddress(&p_Bu, g_Bfu);
    cudaGetSymbolAddress(&p_B2, g_Bf2);

    const int sm1 = 31680 + 6336 + 28672;   // 66688 B
    const int sm2 = 6 * 66 * 72 * 2;        // 57024 B
    cudaFuncSetAttribute((const void*)k_conv1,
                         cudaFuncAttributeMaxDynamicSharedMemorySize, sm1);
    cudaFuncSetAttribute((const void*)k_conv2,
                         cudaFuncAttributeMaxDynamicSharedMemorySize, sm2);

    // 1) downsample (also zeroes g_agg)
    k_down<<<1024, 256>>>(x, w_down, b_down);
    // 2) weight prep: 4608 + 768 + 4608 = 9984 elements
    k_wprep<<<39, 256>>>(w_n1, w_n2);
    // 3) fused edge network + scatter-add (FFMA2)
    k_edge<<<NEDGE, 256>>>(eidx, w_e1, b_e1, w_e2, b_e2);
    // 4) conv1: x halo (2 k16/tap) + up im2col (3 k16 total), single product
    k_conv1<<<4096, 256, sm1>>>(x, w_up, b_up,
        (const uint2*)p_B1, (const uint2*)p_Bu, b_n1);
    // 5) conv2: 64 -> 32, single product
    k_conv2<<<4096, 256, sm2>>>((const uint4*)p_hidf,
        (const uint2*)p_B2, b_n2, out);
}